// round 1
// baseline (speedup 1.0000x reference)
#include <cuda_runtime.h>
#include <math.h>

#define BATCH   2
#define N_SEQ   2048
#define DIM     1024
#define HEADS   16
#define DHEAD   64
#define ROWS    (BATCH * N_SEQ)   // 4096
#define QKV_COLS 3072

// Scratch (no allocations allowed in kernel_launch)
__device__ float g_xn[ROWS * DIM];          // 16 MB
__device__ float g_qkv[ROWS * QKV_COLS];    // 48 MB
__device__ float g_attn[ROWS * DIM];        // 16 MB

// ---------------------------------------------------------------------------
// RMSNorm: y = x / max(||x||, eps) * sqrt(DIM) * (gamma + 1)
// One block per row, 256 threads, 4 floats (1 float4) per thread.
// ---------------------------------------------------------------------------
__global__ __launch_bounds__(256) void rmsnorm_kernel(
    const float* __restrict__ x, const float* __restrict__ gamma)
{
    int row = blockIdx.x;
    int tid = threadIdx.x;
    const float4* xr = (const float4*)(x + (size_t)row * DIM);
    float4*       xo = (float4*)(g_xn + (size_t)row * DIM);
    const float4* g4 = (const float4*)gamma;

    float4 v = xr[tid];
    float ss = v.x * v.x + v.y * v.y + v.z * v.z + v.w * v.w;
    #pragma unroll
    for (int o = 16; o > 0; o >>= 1) ss += __shfl_xor_sync(0xFFFFFFFFu, ss, o);

    __shared__ float warpsum[8];
    if ((tid & 31) == 0) warpsum[tid >> 5] = ss;
    __syncthreads();
    float sum = 0.f;
    #pragma unroll
    for (int i = 0; i < 8; i++) sum += warpsum[i];

    float norm = fmaxf(sqrtf(sum), 1e-12f);
    float inv  = 32.0f / norm;   // sqrt(1024) / norm

    float4 g = g4[tid];
    float4 o;
    o.x = v.x * inv * (g.x + 1.0f);
    o.y = v.y * inv * (g.y + 1.0f);
    o.z = v.z * inv * (g.z + 1.0f);
    o.w = v.w * inv * (g.w + 1.0f);
    xo[tid] = o;
}

// ---------------------------------------------------------------------------
// SGEMM: C[M, NCOLS] = A[M, KDIM] @ B[KDIM, NCOLS]
// 128x128 block tile, BK=8, 256 threads, 8x8 per-thread microtile.
// M = ROWS (4096) always; NCOLS/KDIM compile-time.
// ---------------------------------------------------------------------------
template<int NCOLS, int KDIM>
__device__ __forceinline__ void sgemm_impl(
    const float* __restrict__ A, const float* __restrict__ Bm, float* __restrict__ C)
{
    __shared__ float As[8][132];   // padded to dodge store conflicts
    __shared__ float Bs[8][128];

    int tid = threadIdx.x;
    int m0 = blockIdx.y * 128;
    int n0 = blockIdx.x * 128;
    int ty = tid >> 4, tx = tid & 15;

    float acc[8][8];
    #pragma unroll
    for (int i = 0; i < 8; i++)
        #pragma unroll
        for (int j = 0; j < 8; j++) acc[i][j] = 0.f;

    int aRow = tid >> 1, aCol = (tid & 1) * 4;
    int bRow = tid >> 5, bCol = (tid & 31) * 4;
    const float* Aptr = A  + (size_t)(m0 + aRow) * KDIM + aCol;
    const float* Bptr = Bm + (size_t)bRow * NCOLS + n0 + bCol;

    for (int k0 = 0; k0 < KDIM; k0 += 8) {
        float4 av = *(const float4*)Aptr;  Aptr += 8;
        float4 bv = *(const float4*)Bptr;  Bptr += (size_t)8 * NCOLS;

        As[aCol + 0][aRow] = av.x;
        As[aCol + 1][aRow] = av.y;
        As[aCol + 2][aRow] = av.z;
        As[aCol + 3][aRow] = av.w;
        *(float4*)&Bs[bRow][bCol] = bv;
        __syncthreads();

        #pragma unroll
        for (int k = 0; k < 8; k++) {
            float4 a0 = *(const float4*)&As[k][ty * 8];
            float4 a1 = *(const float4*)&As[k][ty * 8 + 4];
            float4 b0 = *(const float4*)&Bs[k][tx * 8];
            float4 b1 = *(const float4*)&Bs[k][tx * 8 + 4];
            float a[8] = {a0.x, a0.y, a0.z, a0.w, a1.x, a1.y, a1.z, a1.w};
            float b[8] = {b0.x, b0.y, b0.z, b0.w, b1.x, b1.y, b1.z, b1.w};
            #pragma unroll
            for (int i = 0; i < 8; i++)
                #pragma unroll
                for (int j = 0; j < 8; j++)
                    acc[i][j] = fmaf(a[i], b[j], acc[i][j]);
        }
        __syncthreads();
    }

    #pragma unroll
    for (int i = 0; i < 8; i++) {
        float* Crow = C + (size_t)(m0 + ty * 8 + i) * NCOLS + n0 + tx * 8;
        *(float4*)Crow       = make_float4(acc[i][0], acc[i][1], acc[i][2], acc[i][3]);
        *(float4*)(Crow + 4) = make_float4(acc[i][4], acc[i][5], acc[i][6], acc[i][7]);
    }
}

__global__ __launch_bounds__(256) void qkv_gemm_kernel(const float* __restrict__ w_qkv)
{
    sgemm_impl<QKV_COLS, DIM>(g_xn, w_qkv, g_qkv);
}

__global__ __launch_bounds__(256) void out_gemm_kernel(
    const float* __restrict__ w_out, float* __restrict__ out)
{
    sgemm_impl<DIM, DIM>(g_attn, w_out, out);
}

// ---------------------------------------------------------------------------
// Flash attention, fp32. One thread = one query row. 128 q-rows per block.
// K/V tiles of 32 x 64 staged in SMEM; online softmax; q & O in registers.
// qkv layout: [b*n, 3*1024] with q at col h*64, k at 1024 + h*64, v at 2048 + h*64.
// Output written to g_attn as [b*n, h*64 + d] so out-proj is a plain GEMM.
// ---------------------------------------------------------------------------
__global__ __launch_bounds__(128) void flash_attn_kernel()
{
    __shared__ float Ks[32][64];
    __shared__ float Vs[32][64];

    int bh = blockIdx.y;
    int b = bh >> 4, h = bh & 15;
    int tid = threadIdx.x;
    int row = blockIdx.x * 128 + tid;

    const float* base = g_qkv + (size_t)b * N_SEQ * QKV_COLS;
    const float* qptr = base + (size_t)row * QKV_COLS + h * DHEAD;

    float q[64];
    #pragma unroll
    for (int d4 = 0; d4 < 16; d4++) {
        float4 v = *(const float4*)(qptr + d4 * 4);
        q[d4 * 4 + 0] = v.x * 0.125f;   // 64^-0.5
        q[d4 * 4 + 1] = v.y * 0.125f;
        q[d4 * 4 + 2] = v.z * 0.125f;
        q[d4 * 4 + 3] = v.w * 0.125f;
    }

    float O[64];
    #pragma unroll
    for (int d = 0; d < 64; d++) O[d] = 0.f;
    float m = -INFINITY, l = 0.f;

    for (int kb = 0; kb < N_SEQ; kb += 32) {
        // Cooperative K/V tile load: 32 rows x 64 cols each
        #pragma unroll
        for (int t = 0; t < 4; t++) {
            int idx = tid + t * 128;           // 0..511
            int r = idx >> 4, c = (idx & 15) * 4;
            const float* src = base + (size_t)(kb + r) * QKV_COLS + h * DHEAD + c;
            *(float4*)&Ks[r][c] = *(const float4*)(src + 1024);
            *(float4*)&Vs[r][c] = *(const float4*)(src + 2048);
        }
        __syncthreads();

        float s[32];
        #pragma unroll
        for (int j = 0; j < 32; j++) {
            float acc = 0.f;
            #pragma unroll
            for (int d4 = 0; d4 < 16; d4++) {
                float4 kk = *(const float4*)&Ks[j][d4 * 4];
                acc = fmaf(q[d4 * 4 + 0], kk.x, acc);
                acc = fmaf(q[d4 * 4 + 1], kk.y, acc);
                acc = fmaf(q[d4 * 4 + 2], kk.z, acc);
                acc = fmaf(q[d4 * 4 + 3], kk.w, acc);
            }
            s[j] = acc;
        }

        float mt = m;
        #pragma unroll
        for (int j = 0; j < 32; j++) mt = fmaxf(mt, s[j]);
        float alpha = __expf(m - mt);
        m = mt;
        l *= alpha;
        #pragma unroll
        for (int d = 0; d < 64; d++) O[d] *= alpha;

        #pragma unroll
        for (int j = 0; j < 32; j++) {
            float p = __expf(s[j] - mt);
            l += p;
            #pragma unroll
            for (int d4 = 0; d4 < 16; d4++) {
                float4 vv = *(const float4*)&Vs[j][d4 * 4];
                O[d4 * 4 + 0] = fmaf(p, vv.x, O[d4 * 4 + 0]);
                O[d4 * 4 + 1] = fmaf(p, vv.y, O[d4 * 4 + 1]);
                O[d4 * 4 + 2] = fmaf(p, vv.z, O[d4 * 4 + 2]);
                O[d4 * 4 + 3] = fmaf(p, vv.w, O[d4 * 4 + 3]);
            }
        }
        __syncthreads();
    }

    float inv = 1.0f / l;
    float* optr = g_attn + (size_t)(b * N_SEQ + row) * DIM + h * DHEAD;
    #pragma unroll
    for (int d4 = 0; d4 < 16; d4++) {
        float4 o;
        o.x = O[d4 * 4 + 0] * inv;
        o.y = O[d4 * 4 + 1] * inv;
        o.z = O[d4 * 4 + 2] * inv;
        o.w = O[d4 * 4 + 3] * inv;
        *(float4*)(optr + d4 * 4) = o;
    }
}

// ---------------------------------------------------------------------------
extern "C" void kernel_launch(void* const* d_in, const int* in_sizes, int n_in,
                              void* d_out, int out_size)
{
    const float* x     = (const float*)d_in[0];
    const float* gamma = (const float*)d_in[1];
    const float* w_qkv = (const float*)d_in[2];
    const float* w_out = (const float*)d_in[3];
    float* out = (float*)d_out;

    rmsnorm_kernel<<<ROWS, 256>>>(x, gamma);
    qkv_gemm_kernel<<<dim3(QKV_COLS / 128, ROWS / 128), 256>>>(w_qkv);
    flash_attn_kernel<<<dim3(N_SEQ / 128, BATCH * HEADS), 128>>>();
    out_gemm_kernel<<<dim3(DIM / 128, ROWS / 128), 256>>>(w_out, out);
}

// round 2
// speedup vs baseline: 1.2768x; 1.2768x over previous
#include <cuda_runtime.h>
#include <math.h>
#include <stdint.h>

#define BATCH   2
#define N_SEQ   2048
#define DIM     1024
#define HEADS   16
#define DHEAD   64
#define ROWS    (BATCH * N_SEQ)   // 4096
#define QKV_COLS 3072

// Scratch (no allocations allowed in kernel_launch)
__device__ float g_xn[ROWS * DIM];          // 16 MB
__device__ float g_qkv[ROWS * QKV_COLS];    // 48 MB
__device__ float g_attn[ROWS * DIM];        // 16 MB

// ---------------------------------------------------------------------------
// RMSNorm: y = x / max(||x||, eps) * sqrt(DIM) * (gamma + 1)
// ---------------------------------------------------------------------------
__global__ __launch_bounds__(256) void rmsnorm_kernel(
    const float* __restrict__ x, const float* __restrict__ gamma)
{
    int row = blockIdx.x;
    int tid = threadIdx.x;
    const float4* xr = (const float4*)(x + (size_t)row * DIM);
    float4*       xo = (float4*)(g_xn + (size_t)row * DIM);
    const float4* g4 = (const float4*)gamma;

    float4 v = xr[tid];
    float ss = v.x * v.x + v.y * v.y + v.z * v.z + v.w * v.w;
    #pragma unroll
    for (int o = 16; o > 0; o >>= 1) ss += __shfl_xor_sync(0xFFFFFFFFu, ss, o);

    __shared__ float warpsum[8];
    if ((tid & 31) == 0) warpsum[tid >> 5] = ss;
    __syncthreads();
    float sum = 0.f;
    #pragma unroll
    for (int i = 0; i < 8; i++) sum += warpsum[i];

    float norm = fmaxf(sqrtf(sum), 1e-12f);
    float inv  = 32.0f / norm;   // sqrt(1024) / norm

    float4 g = g4[tid];
    float4 o;
    o.x = v.x * inv * (g.x + 1.0f);
    o.y = v.y * inv * (g.y + 1.0f);
    o.z = v.z * inv * (g.z + 1.0f);
    o.w = v.w * inv * (g.w + 1.0f);
    xo[tid] = o;
}

// ---------------------------------------------------------------------------
// tf32 tensor-core GEMM: C[M, NCOLS] = A[M, KDIM] @ B[KDIM, NCOLS]
// 128x128x32 block tile, 256 threads = 8 warps (4 along M x 2 along N).
// Warp tile 32x64 -> 2x8 grid of m16n8k8 mma per k=8 chunk.
// ---------------------------------------------------------------------------
__device__ __forceinline__ uint32_t f2tf32(float f)
{
    uint32_t r;
    asm("cvt.rna.tf32.f32 %0, %1;" : "=r"(r) : "f"(f));
    return r;
}

__device__ __forceinline__ void mma_tf32(
    float c[4], const uint32_t a[4], const uint32_t b[2])
{
    asm volatile(
        "mma.sync.aligned.m16n8k8.row.col.f32.tf32.tf32.f32 "
        "{%0,%1,%2,%3}, {%4,%5,%6,%7}, {%8,%9}, {%0,%1,%2,%3};"
        : "+f"(c[0]), "+f"(c[1]), "+f"(c[2]), "+f"(c[3])
        : "r"(a[0]), "r"(a[1]), "r"(a[2]), "r"(a[3]), "r"(b[0]), "r"(b[1]));
}

template<int NCOLS, int KDIM>
__device__ __forceinline__ void mma_gemm_impl(
    const float* __restrict__ A, const float* __restrict__ Bm, float* __restrict__ C)
{
    __shared__ float As[128][36];   // 4g+tig bank pattern: conflict-free
    __shared__ float Bs[32][136];   // 8tig+g bank pattern: conflict-free

    const int tid  = threadIdx.x;
    const int lane = tid & 31;
    const int wid  = tid >> 5;
    const int g    = lane >> 2;     // group id 0..7
    const int tig  = lane & 3;      // thread-in-group 0..3
    const int warp_m = wid & 3;     // 4 m-tiles of 32 rows
    const int warp_n = wid >> 2;    // 2 n-tiles of 64 cols

    const int m0 = blockIdx.y * 128;
    const int n0 = blockIdx.x * 128;

    // Global load indexing: A tile 128x32, B tile 32x128, 4 float4 each/thread
    const int aRow = tid >> 1;            // 0..127
    const int aCol = (tid & 1) * 16;      // 0 or 16
    const int bRow = tid >> 3;            // 0..31
    const int bCol = (tid & 7) * 16;      // 0,16,...,112

    float acc[2][8][4];
    #pragma unroll
    for (int i = 0; i < 2; i++)
        #pragma unroll
        for (int j = 0; j < 8; j++)
            #pragma unroll
            for (int r = 0; r < 4; r++) acc[i][j][r] = 0.f;

    // Prefetch first tile into registers
    float4 av[4], bv[4];
    {
        const float4* Ap = (const float4*)(A  + (size_t)(m0 + aRow) * KDIM + aCol);
        const float4* Bp = (const float4*)(Bm + (size_t)bRow * NCOLS + n0 + bCol);
        #pragma unroll
        for (int i = 0; i < 4; i++) { av[i] = Ap[i]; bv[i] = Bp[i]; }
    }

    for (int k0 = 0; k0 < KDIM; k0 += 32) {
        __syncthreads();   // previous compute done before overwriting smem
        #pragma unroll
        for (int i = 0; i < 4; i++) {
            *(float4*)&As[aRow][aCol + 4 * i] = av[i];
            *(float4*)&Bs[bRow][bCol + 4 * i] = bv[i];
        }
        __syncthreads();

        // Prefetch next tile while computing this one
        if (k0 + 32 < KDIM) {
            const float4* Ap = (const float4*)(A  + (size_t)(m0 + aRow) * KDIM + (k0 + 32) + aCol);
            const float4* Bp = (const float4*)(Bm + (size_t)(k0 + 32 + bRow) * NCOLS + n0 + bCol);
            #pragma unroll
            for (int i = 0; i < 4; i++) { av[i] = Ap[i]; bv[i] = Bp[i]; }
        }

        #pragma unroll
        for (int kc = 0; kc < 4; kc++) {
            const int k = kc * 8;
            uint32_t afr[2][4];
            #pragma unroll
            for (int i = 0; i < 2; i++) {
                const int mb = warp_m * 32 + i * 16;
                afr[i][0] = f2tf32(As[mb + g    ][k + tig]);
                afr[i][1] = f2tf32(As[mb + g + 8][k + tig]);
                afr[i][2] = f2tf32(As[mb + g    ][k + tig + 4]);
                afr[i][3] = f2tf32(As[mb + g + 8][k + tig + 4]);
            }
            #pragma unroll
            for (int j = 0; j < 8; j++) {
                const int n = warp_n * 64 + j * 8 + g;
                uint32_t bfr[2];
                bfr[0] = f2tf32(Bs[k + tig    ][n]);
                bfr[1] = f2tf32(Bs[k + tig + 4][n]);
                mma_tf32(acc[0][j], afr[0], bfr);
                mma_tf32(acc[1][j], afr[1], bfr);
            }
        }
    }

    // Epilogue: c0/c1 at (row, 2*tig), c2/c3 at (row+8, 2*tig)
    #pragma unroll
    for (int i = 0; i < 2; i++) {
        const int row = m0 + warp_m * 32 + i * 16 + g;
        #pragma unroll
        for (int j = 0; j < 8; j++) {
            const int col = n0 + warp_n * 64 + j * 8 + 2 * tig;
            float2 lo = make_float2(acc[i][j][0], acc[i][j][1]);
            float2 hi = make_float2(acc[i][j][2], acc[i][j][3]);
            *(float2*)&C[(size_t)row * NCOLS + col]       = lo;
            *(float2*)&C[(size_t)(row + 8) * NCOLS + col] = hi;
        }
    }
}

__global__ __launch_bounds__(256, 2) void qkv_gemm_kernel(const float* __restrict__ w_qkv)
{
    mma_gemm_impl<QKV_COLS, DIM>(g_xn, w_qkv, g_qkv);
}

__global__ __launch_bounds__(256, 2) void out_gemm_kernel(
    const float* __restrict__ w_out, float* __restrict__ out)
{
    mma_gemm_impl<DIM, DIM>(g_attn, w_out, out);
}

// ---------------------------------------------------------------------------
// Flash attention, fp32 SIMT (unchanged this round; tensor-core target next).
// ---------------------------------------------------------------------------
__global__ __launch_bounds__(128) void flash_attn_kernel()
{
    __shared__ float Ks[32][64];
    __shared__ float Vs[32][64];

    int bh = blockIdx.y;
    int b = bh >> 4, h = bh & 15;
    int tid = threadIdx.x;
    int row = blockIdx.x * 128 + tid;

    const float* base = g_qkv + (size_t)b * N_SEQ * QKV_COLS;
    const float* qptr = base + (size_t)row * QKV_COLS + h * DHEAD;

    float q[64];
    #pragma unroll
    for (int d4 = 0; d4 < 16; d4++) {
        float4 v = *(const float4*)(qptr + d4 * 4);
        q[d4 * 4 + 0] = v.x * 0.125f;
        q[d4 * 4 + 1] = v.y * 0.125f;
        q[d4 * 4 + 2] = v.z * 0.125f;
        q[d4 * 4 + 3] = v.w * 0.125f;
    }

    float O[64];
    #pragma unroll
    for (int d = 0; d < 64; d++) O[d] = 0.f;
    float m = -INFINITY, l = 0.f;

    for (int kb = 0; kb < N_SEQ; kb += 32) {
        #pragma unroll
        for (int t = 0; t < 4; t++) {
            int idx = tid + t * 128;
            int r = idx >> 4, c = (idx & 15) * 4;
            const float* src = base + (size_t)(kb + r) * QKV_COLS + h * DHEAD + c;
            *(float4*)&Ks[r][c] = *(const float4*)(src + 1024);
            *(float4*)&Vs[r][c] = *(const float4*)(src + 2048);
        }
        __syncthreads();

        float s[32];
        #pragma unroll
        for (int j = 0; j < 32; j++) {
            float acc = 0.f;
            #pragma unroll
            for (int d4 = 0; d4 < 16; d4++) {
                float4 kk = *(const float4*)&Ks[j][d4 * 4];
                acc = fmaf(q[d4 * 4 + 0], kk.x, acc);
                acc = fmaf(q[d4 * 4 + 1], kk.y, acc);
                acc = fmaf(q[d4 * 4 + 2], kk.z, acc);
                acc = fmaf(q[d4 * 4 + 3], kk.w, acc);
            }
            s[j] = acc;
        }

        float mt = m;
        #pragma unroll
        for (int j = 0; j < 32; j++) mt = fmaxf(mt, s[j]);
        float alpha = __expf(m - mt);
        m = mt;
        l *= alpha;
        #pragma unroll
        for (int d = 0; d < 64; d++) O[d] *= alpha;

        #pragma unroll
        for (int j = 0; j < 32; j++) {
            float p = __expf(s[j] - mt);
            l += p;
            #pragma unroll
            for (int d4 = 0; d4 < 16; d4++) {
                float4 vv = *(const float4*)&Vs[j][d4 * 4];
                O[d4 * 4 + 0] = fmaf(p, vv.x, O[d4 * 4 + 0]);
                O[d4 * 4 + 1] = fmaf(p, vv.y, O[d4 * 4 + 1]);
                O[d4 * 4 + 2] = fmaf(p, vv.z, O[d4 * 4 + 2]);
                O[d4 * 4 + 3] = fmaf(p, vv.w, O[d4 * 4 + 3]);
            }
        }
        __syncthreads();
    }

    float inv = 1.0f / l;
    float* optr = g_attn + (size_t)(b * N_SEQ + row) * DIM + h * DHEAD;
    #pragma unroll
    for (int d4 = 0; d4 < 16; d4++) {
        float4 o;
        o.x = O[d4 * 4 + 0] * inv;
        o.y = O[d4 * 4 + 1] * inv;
        o.z = O[d4 * 4 + 2] * inv;
        o.w = O[d4 * 4 + 3] * inv;
        *(float4*)(optr + d4 * 4) = o;
    }
}

// ---------------------------------------------------------------------------
extern "C" void kernel_launch(void* const* d_in, const int* in_sizes, int n_in,
                              void* d_out, int out_size)
{
    const float* x     = (const float*)d_in[0];
    const float* gamma = (const float*)d_in[1];
    const float* w_qkv = (const float*)d_in[2];
    const float* w_out = (const float*)d_in[3];
    float* out = (float*)d_out;

    rmsnorm_kernel<<<ROWS, 256>>>(x, gamma);
    qkv_gemm_kernel<<<dim3(QKV_COLS / 128, ROWS / 128), 256>>>(w_qkv);
    flash_attn_kernel<<<dim3(N_SEQ / 128, BATCH * HEADS), 128>>>();
    out_gemm_kernel<<<dim3(DIM / 128, ROWS / 128), 256>>>(w_out, out);
}

// round 3
// speedup vs baseline: 3.3021x; 2.5863x over previous
#include <cuda_runtime.h>
#include <cuda_fp16.h>
#include <math.h>
#include <stdint.h>

#define BATCH   2
#define N_SEQ   2048
#define DIM     1024
#define HEADS   16
#define DHEAD   64
#define ROWS    (BATCH * N_SEQ)   // 4096
#define QKV_COLS 3072

// Scratch (no allocations allowed in kernel_launch)
__device__ float g_xn[ROWS * DIM];          // 16 MB
__device__ float g_qkv[ROWS * QKV_COLS];    // 48 MB
__device__ float g_attn[ROWS * DIM];        // 16 MB

// ---------------------------------------------------------------------------
__device__ __forceinline__ uint32_t f2tf32(float f)
{
    uint32_t r;
    asm("cvt.rna.tf32.f32 %0, %1;" : "=r"(r) : "f"(f));
    return r;
}

__device__ __forceinline__ void mma_tf32(
    float c[4], const uint32_t a[4], const uint32_t b[2])
{
    asm volatile(
        "mma.sync.aligned.m16n8k8.row.col.f32.tf32.tf32.f32 "
        "{%0,%1,%2,%3}, {%4,%5,%6,%7}, {%8,%9}, {%0,%1,%2,%3};"
        : "+f"(c[0]), "+f"(c[1]), "+f"(c[2]), "+f"(c[3])
        : "r"(a[0]), "r"(a[1]), "r"(a[2]), "r"(a[3]), "r"(b[0]), "r"(b[1]));
}

__device__ __forceinline__ void mma_f16(
    float c[4], const uint32_t a[4], const uint32_t b0, const uint32_t b1)
{
    asm volatile(
        "mma.sync.aligned.m16n8k16.row.col.f32.f16.f16.f32 "
        "{%0,%1,%2,%3}, {%4,%5,%6,%7}, {%8,%9}, {%0,%1,%2,%3};"
        : "+f"(c[0]), "+f"(c[1]), "+f"(c[2]), "+f"(c[3])
        : "r"(a[0]), "r"(a[1]), "r"(a[2]), "r"(a[3]), "r"(b0), "r"(b1));
}

// ---------------------------------------------------------------------------
// RMSNorm
// ---------------------------------------------------------------------------
__global__ __launch_bounds__(256) void rmsnorm_kernel(
    const float* __restrict__ x, const float* __restrict__ gamma)
{
    int row = blockIdx.x;
    int tid = threadIdx.x;
    const float4* xr = (const float4*)(x + (size_t)row * DIM);
    float4*       xo = (float4*)(g_xn + (size_t)row * DIM);
    const float4* g4 = (const float4*)gamma;

    float4 v = xr[tid];
    float ss = v.x * v.x + v.y * v.y + v.z * v.z + v.w * v.w;
    #pragma unroll
    for (int o = 16; o > 0; o >>= 1) ss += __shfl_xor_sync(0xFFFFFFFFu, ss, o);

    __shared__ float warpsum[8];
    if ((tid & 31) == 0) warpsum[tid >> 5] = ss;
    __syncthreads();
    float sum = 0.f;
    #pragma unroll
    for (int i = 0; i < 8; i++) sum += warpsum[i];

    float norm = fmaxf(sqrtf(sum), 1e-12f);
    float inv  = 32.0f / norm;

    float4 g = g4[tid];
    float4 o;
    o.x = v.x * inv * (g.x + 1.0f);
    o.y = v.y * inv * (g.y + 1.0f);
    o.z = v.z * inv * (g.z + 1.0f);
    o.w = v.w * inv * (g.w + 1.0f);
    xo[tid] = o;
}

// ---------------------------------------------------------------------------
// tf32 GEMM, cvt at staging: smem holds tf32 bit patterns.
// 128x128x32 tile, 256 threads, warp tile 32x64.
// ---------------------------------------------------------------------------
template<int NCOLS, int KDIM>
__device__ __forceinline__ void mma_gemm_impl(
    const float* __restrict__ A, const float* __restrict__ Bm, float* __restrict__ C)
{
    __shared__ uint32_t As[128][36];
    __shared__ uint32_t Bs[32][136];

    const int tid  = threadIdx.x;
    const int lane = tid & 31;
    const int wid  = tid >> 5;
    const int g    = lane >> 2;
    const int tig  = lane & 3;
    const int warp_m = wid & 3;
    const int warp_n = wid >> 2;

    const int m0 = blockIdx.y * 128;
    const int n0 = blockIdx.x * 128;

    const int aRow = tid >> 1;
    const int aCol = (tid & 1) * 16;
    const int bRow = tid >> 3;
    const int bCol = (tid & 7) * 16;

    float acc[2][8][4];
    #pragma unroll
    for (int i = 0; i < 2; i++)
        #pragma unroll
        for (int j = 0; j < 8; j++)
            #pragma unroll
            for (int r = 0; r < 4; r++) acc[i][j][r] = 0.f;

    float4 av[4], bv[4];
    {
        const float4* Ap = (const float4*)(A  + (size_t)(m0 + aRow) * KDIM + aCol);
        const float4* Bp = (const float4*)(Bm + (size_t)bRow * NCOLS + n0 + bCol);
        #pragma unroll
        for (int i = 0; i < 4; i++) { av[i] = Ap[i]; bv[i] = Bp[i]; }
    }

    for (int k0 = 0; k0 < KDIM; k0 += 32) {
        __syncthreads();
        #pragma unroll
        for (int i = 0; i < 4; i++) {
            As[aRow][aCol + 4 * i + 0] = f2tf32(av[i].x);
            As[aRow][aCol + 4 * i + 1] = f2tf32(av[i].y);
            As[aRow][aCol + 4 * i + 2] = f2tf32(av[i].z);
            As[aRow][aCol + 4 * i + 3] = f2tf32(av[i].w);
            Bs[bRow][bCol + 4 * i + 0] = f2tf32(bv[i].x);
            Bs[bRow][bCol + 4 * i + 1] = f2tf32(bv[i].y);
            Bs[bRow][bCol + 4 * i + 2] = f2tf32(bv[i].z);
            Bs[bRow][bCol + 4 * i + 3] = f2tf32(bv[i].w);
        }
        __syncthreads();

        if (k0 + 32 < KDIM) {
            const float4* Ap = (const float4*)(A  + (size_t)(m0 + aRow) * KDIM + (k0 + 32) + aCol);
            const float4* Bp = (const float4*)(Bm + (size_t)(k0 + 32 + bRow) * NCOLS + n0 + bCol);
            #pragma unroll
            for (int i = 0; i < 4; i++) { av[i] = Ap[i]; bv[i] = Bp[i]; }
        }

        #pragma unroll
        for (int kc = 0; kc < 4; kc++) {
            const int k = kc * 8;
            uint32_t afr[2][4];
            #pragma unroll
            for (int i = 0; i < 2; i++) {
                const int mb = warp_m * 32 + i * 16;
                afr[i][0] = As[mb + g    ][k + tig];
                afr[i][1] = As[mb + g + 8][k + tig];
                afr[i][2] = As[mb + g    ][k + tig + 4];
                afr[i][3] = As[mb + g + 8][k + tig + 4];
            }
            #pragma unroll
            for (int j = 0; j < 8; j++) {
                const int n = warp_n * 64 + j * 8 + g;
                uint32_t bfr[2];
                bfr[0] = Bs[k + tig    ][n];
                bfr[1] = Bs[k + tig + 4][n];
                mma_tf32(acc[0][j], afr[0], bfr);
                mma_tf32(acc[1][j], afr[1], bfr);
            }
        }
    }

    #pragma unroll
    for (int i = 0; i < 2; i++) {
        const int row = m0 + warp_m * 32 + i * 16 + g;
        #pragma unroll
        for (int j = 0; j < 8; j++) {
            const int col = n0 + warp_n * 64 + j * 8 + 2 * tig;
            float2 lo = make_float2(acc[i][j][0], acc[i][j][1]);
            float2 hi = make_float2(acc[i][j][2], acc[i][j][3]);
            *(float2*)&C[(size_t)row * NCOLS + col]       = lo;
            *(float2*)&C[(size_t)(row + 8) * NCOLS + col] = hi;
        }
    }
}

__global__ __launch_bounds__(256, 2) void qkv_gemm_kernel(const float* __restrict__ w_qkv)
{
    mma_gemm_impl<QKV_COLS, DIM>(g_xn, w_qkv, g_qkv);
}

__global__ __launch_bounds__(256, 2) void out_gemm_kernel(
    const float* __restrict__ w_out, float* __restrict__ out)
{
    mma_gemm_impl<DIM, DIM>(g_attn, w_out, out);
}

// ---------------------------------------------------------------------------
// Tensor-core flash attention.
// Block: 128 q-rows x one (b,h). 4 warps, each warp 32 q-rows (2 m16 tiles).
// K-tile: 64 keys. QK^T in tf32 mma (K smem as tf32), softmax in fp32,
// P@V in fp16 m16n8k16 (C-frag of S == A-frag of P, no shuffle/smem needed;
// V staged transposed in smem as fp16).
// ---------------------------------------------------------------------------
__global__ __launch_bounds__(128) void flash_attn_kernel()
{
    __shared__ uint32_t Ks[64][68];   // tf32 bits, [key][dim], pad 68 -> 4g+tig
    __shared__ __half   Vsh[64][72];  // [dim][key], pad 72 halves (36 words)

    const int tid  = threadIdx.x;
    const int lane = tid & 31;
    const int wid  = tid >> 5;
    const int g    = lane >> 2;
    const int tig  = lane & 3;

    const int bh = blockIdx.y;
    const int b  = bh >> 4, h = bh & 15;
    const int qrow0 = blockIdx.x * 128 + wid * 32;

    const float* base = g_qkv + (size_t)b * N_SEQ * QKV_COLS;

    // Load Q fragments (once), scaled by dhead^-0.5, as tf32.
    uint32_t aq[2][8][4];
    #pragma unroll
    for (int mt = 0; mt < 2; mt++) {
        const float* qlo = base + (size_t)(qrow0 + mt * 16 + g    ) * QKV_COLS + h * DHEAD;
        const float* qhi = base + (size_t)(qrow0 + mt * 16 + g + 8) * QKV_COLS + h * DHEAD;
        #pragma unroll
        for (int kc = 0; kc < 8; kc++) {
            aq[mt][kc][0] = f2tf32(qlo[kc * 8 + tig    ] * 0.125f);
            aq[mt][kc][1] = f2tf32(qhi[kc * 8 + tig    ] * 0.125f);
            aq[mt][kc][2] = f2tf32(qlo[kc * 8 + tig + 4] * 0.125f);
            aq[mt][kc][3] = f2tf32(qhi[kc * 8 + tig + 4] * 0.125f);
        }
    }

    float Oa[2][8][4];
    #pragma unroll
    for (int mt = 0; mt < 2; mt++)
        #pragma unroll
        for (int dt = 0; dt < 8; dt++)
            #pragma unroll
            for (int r = 0; r < 4; r++) Oa[mt][dt][r] = 0.f;

    float m[2][2] = {{-INFINITY, -INFINITY}, {-INFINITY, -INFINITY}};
    float l[2][2] = {{0.f, 0.f}, {0.f, 0.f}};   // per-lane partial row sums

    const int sr = tid >> 4;          // 0..7
    const int sc = (tid & 15) * 4;    // 0..60

    for (int kb = 0; kb < N_SEQ; kb += 64) {
        // Stage K (tf32) and V (fp16, transposed).
        float4 kv[8], vv[8];
        #pragma unroll
        for (int it = 0; it < 8; it++) {
            const float* src = base + (size_t)(kb + it * 8 + sr) * QKV_COLS + h * DHEAD + sc;
            kv[it] = *(const float4*)(src + 1024);
            vv[it] = *(const float4*)(src + 2048);
        }
        __syncthreads();
        #pragma unroll
        for (int it = 0; it < 8; it++) {
            const int r = it * 8 + sr;
            Ks[r][sc + 0] = f2tf32(kv[it].x);
            Ks[r][sc + 1] = f2tf32(kv[it].y);
            Ks[r][sc + 2] = f2tf32(kv[it].z);
            Ks[r][sc + 3] = f2tf32(kv[it].w);
            Vsh[sc + 0][r] = __float2half(vv[it].x);
            Vsh[sc + 1][r] = __float2half(vv[it].y);
            Vsh[sc + 2][r] = __float2half(vv[it].z);
            Vsh[sc + 3][r] = __float2half(vv[it].w);
        }
        __syncthreads();

        // S = Q @ K^T  (tf32)
        float s[2][8][4];
        #pragma unroll
        for (int mt = 0; mt < 2; mt++)
            #pragma unroll
            for (int j = 0; j < 8; j++)
                #pragma unroll
                for (int r = 0; r < 4; r++) s[mt][j][r] = 0.f;

        #pragma unroll
        for (int kc = 0; kc < 8; kc++) {
            #pragma unroll
            for (int j = 0; j < 8; j++) {
                uint32_t bfr[2];
                bfr[0] = Ks[j * 8 + g][kc * 8 + tig    ];
                bfr[1] = Ks[j * 8 + g][kc * 8 + tig + 4];
                mma_tf32(s[0][j], aq[0][kc], bfr);
                mma_tf32(s[1][j], aq[1][kc], bfr);
            }
        }

        // Online softmax
        float nm[2][2], alpha[2][2];
        #pragma unroll
        for (int mt = 0; mt < 2; mt++) {
            float mlo = m[mt][0], mhi = m[mt][1];
            #pragma unroll
            for (int j = 0; j < 8; j++) {
                mlo = fmaxf(mlo, fmaxf(s[mt][j][0], s[mt][j][1]));
                mhi = fmaxf(mhi, fmaxf(s[mt][j][2], s[mt][j][3]));
            }
            mlo = fmaxf(mlo, __shfl_xor_sync(0xFFFFFFFFu, mlo, 1));
            mlo = fmaxf(mlo, __shfl_xor_sync(0xFFFFFFFFu, mlo, 2));
            mhi = fmaxf(mhi, __shfl_xor_sync(0xFFFFFFFFu, mhi, 1));
            mhi = fmaxf(mhi, __shfl_xor_sync(0xFFFFFFFFu, mhi, 2));
            nm[mt][0] = mlo; nm[mt][1] = mhi;
            alpha[mt][0] = __expf(m[mt][0] - mlo);
            alpha[mt][1] = __expf(m[mt][1] - mhi);
            m[mt][0] = mlo; m[mt][1] = mhi;
        }

        // exp + pack P as fp16 A-fragments, rescale O and l
        uint32_t pa[2][4][4];   // [mt][k16 chunk jj][4 regs]
        #pragma unroll
        for (int mt = 0; mt < 2; mt++) {
            float rs_lo = 0.f, rs_hi = 0.f;
            #pragma unroll
            for (int jj = 0; jj < 4; jj++) {
                float p00 = __expf(s[mt][2*jj  ][0] - nm[mt][0]);
                float p01 = __expf(s[mt][2*jj  ][1] - nm[mt][0]);
                float p02 = __expf(s[mt][2*jj  ][2] - nm[mt][1]);
                float p03 = __expf(s[mt][2*jj  ][3] - nm[mt][1]);
                float p10 = __expf(s[mt][2*jj+1][0] - nm[mt][0]);
                float p11 = __expf(s[mt][2*jj+1][1] - nm[mt][0]);
                float p12 = __expf(s[mt][2*jj+1][2] - nm[mt][1]);
                float p13 = __expf(s[mt][2*jj+1][3] - nm[mt][1]);
                rs_lo += p00 + p01 + p10 + p11;
                rs_hi += p02 + p03 + p12 + p13;
                __half2 h0 = __floats2half2_rn(p00, p01);
                __half2 h1 = __floats2half2_rn(p02, p03);
                __half2 h2 = __floats2half2_rn(p10, p11);
                __half2 h3 = __floats2half2_rn(p12, p13);
                pa[mt][jj][0] = *(uint32_t*)&h0;
                pa[mt][jj][1] = *(uint32_t*)&h1;
                pa[mt][jj][2] = *(uint32_t*)&h2;
                pa[mt][jj][3] = *(uint32_t*)&h3;
            }
            l[mt][0] = l[mt][0] * alpha[mt][0] + rs_lo;
            l[mt][1] = l[mt][1] * alpha[mt][1] + rs_hi;
            #pragma unroll
            for (int dt = 0; dt < 8; dt++) {
                Oa[mt][dt][0] *= alpha[mt][0];
                Oa[mt][dt][1] *= alpha[mt][0];
                Oa[mt][dt][2] *= alpha[mt][1];
                Oa[mt][dt][3] *= alpha[mt][1];
            }
        }

        // O += P @ V  (fp16 m16n8k16)
        #pragma unroll
        for (int jj = 0; jj < 4; jj++) {
            #pragma unroll
            for (int dt = 0; dt < 8; dt++) {
                uint32_t b0 = *(const uint32_t*)&Vsh[dt * 8 + g][jj * 16 + 2 * tig    ];
                uint32_t b1 = *(const uint32_t*)&Vsh[dt * 8 + g][jj * 16 + 2 * tig + 8];
                mma_f16(Oa[0][dt], pa[0][jj], b0, b1);
                mma_f16(Oa[1][dt], pa[1][jj], b0, b1);
            }
        }
    }

    // Reduce l across the 4 lanes of each row, then write O / l.
    #pragma unroll
    for (int mt = 0; mt < 2; mt++) {
        #pragma unroll
        for (int hh = 0; hh < 2; hh++) {
            float lv = l[mt][hh];
            lv += __shfl_xor_sync(0xFFFFFFFFu, lv, 1);
            lv += __shfl_xor_sync(0xFFFFFFFFu, lv, 2);
            l[mt][hh] = 1.0f / lv;
        }
    }

    #pragma unroll
    for (int mt = 0; mt < 2; mt++) {
        const int row_lo = qrow0 + mt * 16 + g;
        float* olo = g_attn + (size_t)(b * N_SEQ + row_lo) * DIM + h * DHEAD;
        float* ohi = olo + (size_t)8 * DIM;
        #pragma unroll
        for (int dt = 0; dt < 8; dt++) {
            const int col = dt * 8 + 2 * tig;
            *(float2*)(olo + col) = make_float2(Oa[mt][dt][0] * l[mt][0],
                                                Oa[mt][dt][1] * l[mt][0]);
            *(float2*)(ohi + col) = make_float2(Oa[mt][dt][2] * l[mt][1],
                                                Oa[mt][dt][3] * l[mt][1]);
        }
    }
}

// ---------------------------------------------------------------------------
extern "C" void kernel_launch(void* const* d_in, const int* in_sizes, int n_in,
                              void* d_out, int out_size)
{
    const float* x     = (const float*)d_in[0];
    const float* gamma = (const float*)d_in[1];
    const float* w_qkv = (const float*)d_in[2];
    const float* w_out = (const float*)d_in[3];
    float* out = (float*)d_out;

    rmsnorm_kernel<<<ROWS, 256>>>(x, gamma);
    qkv_gemm_kernel<<<dim3(QKV_COLS / 128, ROWS / 128), 256>>>(w_qkv);
    flash_attn_kernel<<<dim3(N_SEQ / 128, BATCH * HEADS), 128>>>();
    out_gemm_kernel<<<dim3(DIM / 128, ROWS / 128), 256>>>(w_out, out);
}

// round 4
// speedup vs baseline: 4.5621x; 1.3816x over previous
#include <cuda_runtime.h>
#include <cuda_fp16.h>
#include <math.h>
#include <stdint.h>

#define BATCH   2
#define N_SEQ   2048
#define DIM     1024
#define HEADS   16
#define DHEAD   64
#define ROWS    (BATCH * N_SEQ)   // 4096
#define QKV_COLS 3072

// Scratch (no allocations allowed in kernel_launch)
__device__ float g_xn[ROWS * DIM];          // 16 MB
__device__ float g_qkv[ROWS * QKV_COLS];    // 48 MB
__device__ float g_attn[ROWS * DIM];        // 16 MB

// ---------------------------------------------------------------------------
__device__ __forceinline__ uint32_t smem_u32(const void* p)
{
    return (uint32_t)__cvta_generic_to_shared(p);
}

__device__ __forceinline__ void ldsm_x4(
    uint32_t& r0, uint32_t& r1, uint32_t& r2, uint32_t& r3, uint32_t addr)
{
    asm volatile("ldmatrix.sync.aligned.m8n8.x4.shared.b16 {%0,%1,%2,%3}, [%4];"
                 : "=r"(r0), "=r"(r1), "=r"(r2), "=r"(r3) : "r"(addr));
}

__device__ __forceinline__ void ldsm_x4_trans(
    uint32_t& r0, uint32_t& r1, uint32_t& r2, uint32_t& r3, uint32_t addr)
{
    asm volatile("ldmatrix.sync.aligned.m8n8.x4.trans.shared.b16 {%0,%1,%2,%3}, [%4];"
                 : "=r"(r0), "=r"(r1), "=r"(r2), "=r"(r3) : "r"(addr));
}

__device__ __forceinline__ void mma_f16(
    float c[4], const uint32_t a[4], const uint32_t b0, const uint32_t b1)
{
    asm volatile(
        "mma.sync.aligned.m16n8k16.row.col.f32.f16.f16.f32 "
        "{%0,%1,%2,%3}, {%4,%5,%6,%7}, {%8,%9}, {%0,%1,%2,%3};"
        : "+f"(c[0]), "+f"(c[1]), "+f"(c[2]), "+f"(c[3])
        : "r"(a[0]), "r"(a[1]), "r"(a[2]), "r"(a[3]), "r"(b0), "r"(b1));
}

__device__ __forceinline__ uint32_t h2pack(float a, float b)
{
    __half2 h = __floats2half2_rn(a, b);
    return *(uint32_t*)&h;
}

// ---------------------------------------------------------------------------
// RMSNorm
// ---------------------------------------------------------------------------
__global__ __launch_bounds__(256) void rmsnorm_kernel(
    const float* __restrict__ x, const float* __restrict__ gamma)
{
    int row = blockIdx.x;
    int tid = threadIdx.x;
    const float4* xr = (const float4*)(x + (size_t)row * DIM);
    float4*       xo = (float4*)(g_xn + (size_t)row * DIM);
    const float4* g4 = (const float4*)gamma;

    float4 v = xr[tid];
    float ss = v.x * v.x + v.y * v.y + v.z * v.z + v.w * v.w;
    #pragma unroll
    for (int o = 16; o > 0; o >>= 1) ss += __shfl_xor_sync(0xFFFFFFFFu, ss, o);

    __shared__ float warpsum[8];
    if ((tid & 31) == 0) warpsum[tid >> 5] = ss;
    __syncthreads();
    float sum = 0.f;
    #pragma unroll
    for (int i = 0; i < 8; i++) sum += warpsum[i];

    float norm = fmaxf(sqrtf(sum), 1e-12f);
    float inv  = 32.0f / norm;

    float4 g = g4[tid];
    float4 o;
    o.x = v.x * inv * (g.x + 1.0f);
    o.y = v.y * inv * (g.y + 1.0f);
    o.z = v.z * inv * (g.z + 1.0f);
    o.w = v.w * inv * (g.w + 1.0f);
    xo[tid] = o;
}

// ---------------------------------------------------------------------------
// fp16 tensor-core GEMM: C[M,NCOLS] = A[M,KDIM] @ B[KDIM,NCOLS], fp32 I/O.
// 128x128x32 tile, 256 threads = 8 warps (4 M x 2 N), warp tile 32x64.
// Fragments via ldmatrix; smem strides conflict-free for LDSM.
// ---------------------------------------------------------------------------
template<int NCOLS, int KDIM>
__device__ __forceinline__ void hgemm_impl(
    const float* __restrict__ A, const float* __restrict__ Bm, float* __restrict__ C)
{
    __shared__ __half As[128][40];    // stride 80B = 5 quads (coprime 8)
    __shared__ __half Bs[32][136];    // stride 272B = 17 quads

    const int tid  = threadIdx.x;
    const int lane = tid & 31;
    const int wid  = tid >> 5;
    const int g    = lane >> 2;
    const int tig  = lane & 3;
    const int warp_m = wid & 3;
    const int warp_n = wid >> 2;

    const int m0 = blockIdx.y * 128;
    const int n0 = blockIdx.x * 128;

    const int aRow = tid >> 1;           // 0..127
    const int aCol = (tid & 1) * 16;     // 0/16
    const int bRow = tid >> 3;           // 0..31
    const int bCol = (tid & 7) * 16;     // 0..112

    // ldmatrix per-lane bases
    const uint32_t a_base = smem_u32(&As[warp_m * 32 + (lane & 15)][(lane >> 4) * 8]);
    const uint32_t b_base = smem_u32(&Bs[lane & 15][warp_n * 64 + (lane >> 4) * 8]);

    float acc[2][8][4];
    #pragma unroll
    for (int i = 0; i < 2; i++)
        #pragma unroll
        for (int j = 0; j < 8; j++)
            #pragma unroll
            for (int r = 0; r < 4; r++) acc[i][j][r] = 0.f;

    float4 av[4], bv[4];
    {
        const float4* Ap = (const float4*)(A  + (size_t)(m0 + aRow) * KDIM + aCol);
        const float4* Bp = (const float4*)(Bm + (size_t)bRow * NCOLS + n0 + bCol);
        #pragma unroll
        for (int i = 0; i < 4; i++) { av[i] = Ap[i]; bv[i] = Bp[i]; }
    }

    for (int k0 = 0; k0 < KDIM; k0 += 32) {
        __syncthreads();
        {
            __half2* ad = (__half2*)&As[aRow][aCol];
            __half2* bd = (__half2*)&Bs[bRow][bCol];
            #pragma unroll
            for (int i = 0; i < 4; i++) {
                ad[2 * i    ] = __floats2half2_rn(av[i].x, av[i].y);
                ad[2 * i + 1] = __floats2half2_rn(av[i].z, av[i].w);
                bd[2 * i    ] = __floats2half2_rn(bv[i].x, bv[i].y);
                bd[2 * i + 1] = __floats2half2_rn(bv[i].z, bv[i].w);
            }
        }
        __syncthreads();

        if (k0 + 32 < KDIM) {
            const float4* Ap = (const float4*)(A  + (size_t)(m0 + aRow) * KDIM + (k0 + 32) + aCol);
            const float4* Bp = (const float4*)(Bm + (size_t)(k0 + 32 + bRow) * NCOLS + n0 + bCol);
            #pragma unroll
            for (int i = 0; i < 4; i++) { av[i] = Ap[i]; bv[i] = Bp[i]; }
        }

        #pragma unroll
        for (int kc = 0; kc < 2; kc++) {
            uint32_t a[2][4];
            ldsm_x4(a[0][0], a[0][1], a[0][2], a[0][3], a_base + kc * 32);
            ldsm_x4(a[1][0], a[1][1], a[1][2], a[1][3], a_base + 16 * 80 + kc * 32);

            uint32_t b[8][2];
            #pragma unroll
            for (int jp = 0; jp < 4; jp++) {
                uint32_t d0, d1, d2, d3;
                ldsm_x4_trans(d0, d1, d2, d3, b_base + kc * 16 * 272 + jp * 32);
                b[2 * jp    ][0] = d0; b[2 * jp    ][1] = d1;
                b[2 * jp + 1][0] = d2; b[2 * jp + 1][1] = d3;
            }

            #pragma unroll
            for (int j = 0; j < 8; j++) {
                mma_f16(acc[0][j], a[0], b[j][0], b[j][1]);
                mma_f16(acc[1][j], a[1], b[j][0], b[j][1]);
            }
        }
    }

    #pragma unroll
    for (int i = 0; i < 2; i++) {
        const int row = m0 + warp_m * 32 + i * 16 + g;
        #pragma unroll
        for (int j = 0; j < 8; j++) {
            const int col = n0 + warp_n * 64 + j * 8 + 2 * tig;
            *(float2*)&C[(size_t)row * NCOLS + col]       = make_float2(acc[i][j][0], acc[i][j][1]);
            *(float2*)&C[(size_t)(row + 8) * NCOLS + col] = make_float2(acc[i][j][2], acc[i][j][3]);
        }
    }
}

__global__ __launch_bounds__(256, 2) void qkv_gemm_kernel(const float* __restrict__ w_qkv)
{
    hgemm_impl<QKV_COLS, DIM>(g_xn, w_qkv, g_qkv);
}

__global__ __launch_bounds__(256, 2) void out_gemm_kernel(
    const float* __restrict__ w_out, float* __restrict__ out)
{
    hgemm_impl<DIM, DIM>(g_attn, w_out, out);
}

// ---------------------------------------------------------------------------
// fp16 tensor-core flash attention.
// Block: 128 q-rows x (b,h). 4 warps x 32 q-rows (2 m16 tiles). K-tile 64.
// QK^T and PV both m16n8k16 fp16; softmax fp32. K_h[key][dim], Vsh[dim][key].
// ---------------------------------------------------------------------------
__global__ __launch_bounds__(128) void flash_attn_kernel()
{
    __shared__ __half K_h[64][72];    // stride 144B = 9 quads (coprime 8)
    __shared__ __half Vsh[64][72];

    const int tid  = threadIdx.x;
    const int lane = tid & 31;
    const int wid  = tid >> 5;
    const int g    = lane >> 2;
    const int tig  = lane & 3;

    const int bh = blockIdx.y;
    const int b  = bh >> 4, h = bh & 15;
    const int qrow0 = blockIdx.x * 128 + wid * 32;

    const float* base = g_qkv + (size_t)b * N_SEQ * QKV_COLS;

    // Q fragments (fp16, scaled): aq[mt][kc][0..3]
    uint32_t aq[2][4][4];
    #pragma unroll
    for (int mt = 0; mt < 2; mt++) {
        const float* qlo = base + (size_t)(qrow0 + mt * 16 + g    ) * QKV_COLS + h * DHEAD;
        const float* qhi = base + (size_t)(qrow0 + mt * 16 + g + 8) * QKV_COLS + h * DHEAD;
        #pragma unroll
        for (int kc = 0; kc < 4; kc++) {
            const int c = kc * 16 + 2 * tig;
            aq[mt][kc][0] = h2pack(qlo[c    ] * 0.125f, qlo[c + 1] * 0.125f);
            aq[mt][kc][1] = h2pack(qhi[c    ] * 0.125f, qhi[c + 1] * 0.125f);
            aq[mt][kc][2] = h2pack(qlo[c + 8] * 0.125f, qlo[c + 9] * 0.125f);
            aq[mt][kc][3] = h2pack(qhi[c + 8] * 0.125f, qhi[c + 9] * 0.125f);
        }
    }

    // ldmatrix bases:
    // K (non-trans): matrices keyed by (lane>>4 -> key+8), (lane>>3 &1 -> dim+8)
    const uint32_t kb_base = smem_u32(
        &K_h[(lane & 7) + ((lane >> 4) & 1) * 8][((lane >> 3) & 1) * 8]);
    // V (non-trans): rows = dim, cols = key
    const uint32_t vb_base = smem_u32(
        &Vsh[(lane & 7) + ((lane >> 4) & 1) * 8][((lane >> 3) & 1) * 8]);

    float Oa[2][8][4];
    #pragma unroll
    for (int mt = 0; mt < 2; mt++)
        #pragma unroll
        for (int dt = 0; dt < 8; dt++)
            #pragma unroll
            for (int r = 0; r < 4; r++) Oa[mt][dt][r] = 0.f;

    float m[2][2] = {{-INFINITY, -INFINITY}, {-INFINITY, -INFINITY}};
    float l[2][2] = {{0.f, 0.f}, {0.f, 0.f}};

    const int sr = tid >> 4;          // 0..7
    const int sc = (tid & 15) * 4;    // 0..60

    for (int kb = 0; kb < N_SEQ; kb += 64) {
        float4 kv[8], vv[8];
        #pragma unroll
        for (int it = 0; it < 8; it++) {
            const float* src = base + (size_t)(kb + it * 8 + sr) * QKV_COLS + h * DHEAD + sc;
            kv[it] = *(const float4*)(src + 1024);
            vv[it] = *(const float4*)(src + 2048);
        }
        __syncthreads();
        #pragma unroll
        for (int it = 0; it < 8; it++) {
            const int r = it * 8 + sr;
            __half2* kd = (__half2*)&K_h[r][sc];
            kd[0] = __floats2half2_rn(kv[it].x, kv[it].y);
            kd[1] = __floats2half2_rn(kv[it].z, kv[it].w);
            Vsh[sc + 0][r] = __float2half(vv[it].x);
            Vsh[sc + 1][r] = __float2half(vv[it].y);
            Vsh[sc + 2][r] = __float2half(vv[it].z);
            Vsh[sc + 3][r] = __float2half(vv[it].w);
        }
        __syncthreads();

        // S = Q @ K^T
        float s[2][8][4];
        #pragma unroll
        for (int mt = 0; mt < 2; mt++)
            #pragma unroll
            for (int j = 0; j < 8; j++)
                #pragma unroll
                for (int r = 0; r < 4; r++) s[mt][j][r] = 0.f;

        #pragma unroll
        for (int kc = 0; kc < 4; kc++) {
            #pragma unroll
            for (int jp = 0; jp < 4; jp++) {
                uint32_t d0, d1, d2, d3;
                ldsm_x4(d0, d1, d2, d3, kb_base + jp * 16 * 144 + kc * 32);
                mma_f16(s[0][2 * jp    ], aq[0][kc], d0, d1);
                mma_f16(s[1][2 * jp    ], aq[1][kc], d0, d1);
                mma_f16(s[0][2 * jp + 1], aq[0][kc], d2, d3);
                mma_f16(s[1][2 * jp + 1], aq[1][kc], d2, d3);
            }
        }

        // Online softmax
        float nm[2][2], alpha[2][2];
        #pragma unroll
        for (int mt = 0; mt < 2; mt++) {
            float mlo = m[mt][0], mhi = m[mt][1];
            #pragma unroll
            for (int j = 0; j < 8; j++) {
                mlo = fmaxf(mlo, fmaxf(s[mt][j][0], s[mt][j][1]));
                mhi = fmaxf(mhi, fmaxf(s[mt][j][2], s[mt][j][3]));
            }
            mlo = fmaxf(mlo, __shfl_xor_sync(0xFFFFFFFFu, mlo, 1));
            mlo = fmaxf(mlo, __shfl_xor_sync(0xFFFFFFFFu, mlo, 2));
            mhi = fmaxf(mhi, __shfl_xor_sync(0xFFFFFFFFu, mhi, 1));
            mhi = fmaxf(mhi, __shfl_xor_sync(0xFFFFFFFFu, mhi, 2));
            nm[mt][0] = mlo; nm[mt][1] = mhi;
            alpha[mt][0] = __expf(m[mt][0] - mlo);
            alpha[mt][1] = __expf(m[mt][1] - mhi);
            m[mt][0] = mlo; m[mt][1] = mhi;
        }

        uint32_t pa[2][4][4];
        #pragma unroll
        for (int mt = 0; mt < 2; mt++) {
            float rs_lo = 0.f, rs_hi = 0.f;
            #pragma unroll
            for (int jj = 0; jj < 4; jj++) {
                float p00 = __expf(s[mt][2*jj  ][0] - nm[mt][0]);
                float p01 = __expf(s[mt][2*jj  ][1] - nm[mt][0]);
                float p02 = __expf(s[mt][2*jj  ][2] - nm[mt][1]);
                float p03 = __expf(s[mt][2*jj  ][3] - nm[mt][1]);
                float p10 = __expf(s[mt][2*jj+1][0] - nm[mt][0]);
                float p11 = __expf(s[mt][2*jj+1][1] - nm[mt][0]);
                float p12 = __expf(s[mt][2*jj+1][2] - nm[mt][1]);
                float p13 = __expf(s[mt][2*jj+1][3] - nm[mt][1]);
                rs_lo += p00 + p01 + p10 + p11;
                rs_hi += p02 + p03 + p12 + p13;
                pa[mt][jj][0] = h2pack(p00, p01);
                pa[mt][jj][1] = h2pack(p02, p03);
                pa[mt][jj][2] = h2pack(p10, p11);
                pa[mt][jj][3] = h2pack(p12, p13);
            }
            l[mt][0] = l[mt][0] * alpha[mt][0] + rs_lo;
            l[mt][1] = l[mt][1] * alpha[mt][1] + rs_hi;
            #pragma unroll
            for (int dt = 0; dt < 8; dt++) {
                Oa[mt][dt][0] *= alpha[mt][0];
                Oa[mt][dt][1] *= alpha[mt][0];
                Oa[mt][dt][2] *= alpha[mt][1];
                Oa[mt][dt][3] *= alpha[mt][1];
            }
        }

        // O += P @ V
        #pragma unroll
        for (int jj = 0; jj < 4; jj++) {
            #pragma unroll
            for (int dp = 0; dp < 4; dp++) {
                uint32_t d0, d1, d2, d3;
                ldsm_x4(d0, d1, d2, d3, vb_base + dp * 16 * 144 + jj * 32);
                mma_f16(Oa[0][2 * dp    ], pa[0][jj], d0, d1);
                mma_f16(Oa[1][2 * dp    ], pa[1][jj], d0, d1);
                mma_f16(Oa[0][2 * dp + 1], pa[0][jj], d2, d3);
                mma_f16(Oa[1][2 * dp + 1], pa[1][jj], d2, d3);
            }
        }
    }

    #pragma unroll
    for (int mt = 0; mt < 2; mt++) {
        #pragma unroll
        for (int hh = 0; hh < 2; hh++) {
            float lv = l[mt][hh];
            lv += __shfl_xor_sync(0xFFFFFFFFu, lv, 1);
            lv += __shfl_xor_sync(0xFFFFFFFFu, lv, 2);
            l[mt][hh] = 1.0f / lv;
        }
    }

    #pragma unroll
    for (int mt = 0; mt < 2; mt++) {
        const int row_lo = qrow0 + mt * 16 + g;
        float* olo = g_attn + (size_t)(b * N_SEQ + row_lo) * DIM + h * DHEAD;
        float* ohi = olo + (size_t)8 * DIM;
        #pragma unroll
        for (int dt = 0; dt < 8; dt++) {
            const int col = dt * 8 + 2 * tig;
            *(float2*)(olo + col) = make_float2(Oa[mt][dt][0] * l[mt][0],
                                                Oa[mt][dt][1] * l[mt][0]);
            *(float2*)(ohi + col) = make_float2(Oa[mt][dt][2] * l[mt][1],
                                                Oa[mt][dt][3] * l[mt][1]);
        }
    }
}

// ---------------------------------------------------------------------------
extern "C" void kernel_launch(void* const* d_in, const int* in_sizes, int n_in,
                              void* d_out, int out_size)
{
    const float* x     = (const float*)d_in[0];
    const float* gamma = (const float*)d_in[1];
    const float* w_qkv = (const float*)d_in[2];
    const float* w_out = (const float*)d_in[3];
    float* out = (float*)d_out;

    rmsnorm_kernel<<<ROWS, 256>>>(x, gamma);
    qkv_gemm_kernel<<<dim3(QKV_COLS / 128, ROWS / 128), 256>>>(w_qkv);
    flash_attn_kernel<<<dim3(N_SEQ / 128, BATCH * HEADS), 128>>>();
    out_gemm_kernel<<<dim3(DIM / 128, ROWS / 128), 256>>>(w_out, out);
}

// round 5
// speedup vs baseline: 8.0440x; 1.7632x over previous
#include <cuda_runtime.h>
#include <cuda_fp16.h>
#include <math.h>
#include <stdint.h>

#define BATCH   2
#define N_SEQ   2048
#define DIM     1024
#define HEADS   16
#define DHEAD   64
#define ROWS    (BATCH * N_SEQ)   // 4096
#define QKV_COLS 3072

// fp16 scratch (no allocations allowed in kernel_launch)
__device__ __half g_xn_h[ROWS * DIM];           // 8 MB
__device__ __half g_qkv_h[ROWS * QKV_COLS];     // 24 MB
__device__ __half g_attn_h[ROWS * DIM];         // 8 MB
__device__ __half g_wqkv_h[DIM * QKV_COLS];     // 6 MB
__device__ __half g_wout_h[DIM * DIM];          // 2 MB

// ---------------------------------------------------------------------------
__device__ __forceinline__ uint32_t smem_u32(const void* p)
{
    return (uint32_t)__cvta_generic_to_shared(p);
}

#define CP_ASYNC16(dst, src) \
    asm volatile("cp.async.cg.shared.global [%0], [%1], 16;" :: "r"(dst), "l"(src))
#define CP_COMMIT() asm volatile("cp.async.commit_group;")
#define CP_WAIT(n)  asm volatile("cp.async.wait_group %0;" :: "n"(n))

__device__ __forceinline__ void ldsm_x4(
    uint32_t& r0, uint32_t& r1, uint32_t& r2, uint32_t& r3, uint32_t addr)
{
    asm volatile("ldmatrix.sync.aligned.m8n8.x4.shared.b16 {%0,%1,%2,%3}, [%4];"
                 : "=r"(r0), "=r"(r1), "=r"(r2), "=r"(r3) : "r"(addr));
}

__device__ __forceinline__ void ldsm_x4_trans(
    uint32_t& r0, uint32_t& r1, uint32_t& r2, uint32_t& r3, uint32_t addr)
{
    asm volatile("ldmatrix.sync.aligned.m8n8.x4.trans.shared.b16 {%0,%1,%2,%3}, [%4];"
                 : "=r"(r0), "=r"(r1), "=r"(r2), "=r"(r3) : "r"(addr));
}

__device__ __forceinline__ void mma_f16(
    float c[4], const uint32_t a[4], const uint32_t b0, const uint32_t b1)
{
    asm volatile(
        "mma.sync.aligned.m16n8k16.row.col.f32.f16.f16.f32 "
        "{%0,%1,%2,%3}, {%4,%5,%6,%7}, {%8,%9}, {%0,%1,%2,%3};"
        : "+f"(c[0]), "+f"(c[1]), "+f"(c[2]), "+f"(c[3])
        : "r"(a[0]), "r"(a[1]), "r"(a[2]), "r"(a[3]), "r"(b0), "r"(b1));
}

__device__ __forceinline__ uint32_t h2pack(float a, float b)
{
    __half2 h = __floats2half2_rn(a, b);
    return *(uint32_t*)&h;
}

// ---------------------------------------------------------------------------
// fp32 -> fp16 weight conversion (vectorized), n4 = elements/4
// ---------------------------------------------------------------------------
__global__ __launch_bounds__(256) void f2h_kernel(
    const float* __restrict__ in, __half* __restrict__ out)
{
    int i = blockIdx.x * 256 + threadIdx.x;
    float4 v = ((const float4*)in)[i];
    __half2* o = (__half2*)out;
    o[2 * i    ] = __floats2half2_rn(v.x, v.y);
    o[2 * i + 1] = __floats2half2_rn(v.z, v.w);
}

// ---------------------------------------------------------------------------
// RMSNorm -> fp16
// ---------------------------------------------------------------------------
__global__ __launch_bounds__(256) void rmsnorm_kernel(
    const float* __restrict__ x, const float* __restrict__ gamma)
{
    int row = blockIdx.x;
    int tid = threadIdx.x;
    const float4* xr = (const float4*)(x + (size_t)row * DIM);
    const float4* g4 = (const float4*)gamma;

    float4 v = xr[tid];
    float ss = v.x * v.x + v.y * v.y + v.z * v.z + v.w * v.w;
    #pragma unroll
    for (int o = 16; o > 0; o >>= 1) ss += __shfl_xor_sync(0xFFFFFFFFu, ss, o);

    __shared__ float warpsum[8];
    if ((tid & 31) == 0) warpsum[tid >> 5] = ss;
    __syncthreads();
    float sum = 0.f;
    #pragma unroll
    for (int i = 0; i < 8; i++) sum += warpsum[i];

    float norm = fmaxf(sqrtf(sum), 1e-12f);
    float inv  = 32.0f / norm;

    float4 g = g4[tid];
    __half2* xo = (__half2*)(g_xn_h + (size_t)row * DIM);
    xo[2 * tid    ] = __floats2half2_rn(v.x * inv * (g.x + 1.0f), v.y * inv * (g.y + 1.0f));
    xo[2 * tid + 1] = __floats2half2_rn(v.z * inv * (g.z + 1.0f), v.w * inv * (g.w + 1.0f));
}

// ---------------------------------------------------------------------------
// fp16 GEMM: C[M,NCOLS] = A[M,KDIM] @ B[KDIM,NCOLS]; A,B fp16 in gmem.
// 128x128x32 tile, 256 threads, warp tile 32x64, cp.async double-buffered.
// CT = __half or float output.
// ---------------------------------------------------------------------------
template<int NCOLS, int KDIM, typename CT>
__device__ __forceinline__ void hgemm_impl(
    const __half* __restrict__ A, const __half* __restrict__ Bm, CT* __restrict__ C)
{
    __shared__ __half As[2][128][40];    // row stride 80B = 5 quads
    __shared__ __half Bs[2][32][136];    // row stride 272B = 17 quads

    const int tid  = threadIdx.x;
    const int lane = tid & 31;
    const int wid  = tid >> 5;
    const int g    = lane >> 2;
    const int tig  = lane & 3;
    const int warp_m = wid & 3;
    const int warp_n = wid >> 2;

    const int m0 = blockIdx.y * 128;
    const int n0 = blockIdx.x * 128;

    // cp.async chunk mapping (16B = 8 halves), 2 chunks each for A and B
    const int ac0 = tid,  ac1 = tid + 256;    // A: 512 chunks (128 rows x 4)
    const int aR0 = ac0 >> 2, aC0 = (ac0 & 3) * 8;
    const int aR1 = ac1 >> 2, aC1 = (ac1 & 3) * 8;
    const int bR0 = ac0 >> 4, bC0 = (ac0 & 15) * 8;   // B: 512 chunks (32 x 16)
    const int bR1 = ac1 >> 4, bC1 = (ac1 & 15) * 8;

    const uint32_t sA = smem_u32(As);
    const uint32_t sB = smem_u32(Bs);

    auto issue = [&](int k0, int buf) {
        const uint32_t a_s = sA + buf * (128 * 40 * 2);
        const uint32_t b_s = sB + buf * (32 * 136 * 2);
        CP_ASYNC16(a_s + aR0 * 80 + aC0 * 2,  A  + (size_t)(m0 + aR0) * KDIM + k0 + aC0);
        CP_ASYNC16(a_s + aR1 * 80 + aC1 * 2,  A  + (size_t)(m0 + aR1) * KDIM + k0 + aC1);
        CP_ASYNC16(b_s + bR0 * 272 + bC0 * 2, Bm + (size_t)(k0 + bR0) * NCOLS + n0 + bC0);
        CP_ASYNC16(b_s + bR1 * 272 + bC1 * 2, Bm + (size_t)(k0 + bR1) * NCOLS + n0 + bC1);
        CP_COMMIT();
    };

    float acc[2][8][4];
    #pragma unroll
    for (int i = 0; i < 2; i++)
        #pragma unroll
        for (int j = 0; j < 8; j++)
            #pragma unroll
            for (int r = 0; r < 4; r++) acc[i][j][r] = 0.f;

    const int NT = KDIM / 32;
    issue(0, 0);
    int buf = 0;

    for (int i = 0; i < NT; i++) {
        if (i + 1 < NT) { issue((i + 1) * 32, buf ^ 1); CP_WAIT(1); }
        else            { CP_WAIT(0); }
        __syncthreads();

        const uint32_t a_s = sA + buf * (128 * 40 * 2);
        const uint32_t b_s = sB + buf * (32 * 136 * 2);
        const uint32_t a_base = a_s + (warp_m * 32 + (lane & 15)) * 80 + (lane >> 4) * 16;
        const uint32_t b_base = b_s + (lane & 15) * 272 + (warp_n * 64 + (lane >> 4) * 8) * 2;

        #pragma unroll
        for (int kc = 0; kc < 2; kc++) {
            uint32_t a[2][4];
            ldsm_x4(a[0][0], a[0][1], a[0][2], a[0][3], a_base + kc * 32);
            ldsm_x4(a[1][0], a[1][1], a[1][2], a[1][3], a_base + 16 * 80 + kc * 32);

            uint32_t b[8][2];
            #pragma unroll
            for (int jp = 0; jp < 4; jp++) {
                uint32_t d0, d1, d2, d3;
                ldsm_x4_trans(d0, d1, d2, d3, b_base + kc * 16 * 272 + jp * 32);
                b[2 * jp    ][0] = d0; b[2 * jp    ][1] = d1;
                b[2 * jp + 1][0] = d2; b[2 * jp + 1][1] = d3;
            }

            #pragma unroll
            for (int j = 0; j < 8; j++) {
                mma_f16(acc[0][j], a[0], b[j][0], b[j][1]);
                mma_f16(acc[1][j], a[1], b[j][0], b[j][1]);
            }
        }
        __syncthreads();
        buf ^= 1;
    }

    #pragma unroll
    for (int i = 0; i < 2; i++) {
        const int row = m0 + warp_m * 32 + i * 16 + g;
        #pragma unroll
        for (int j = 0; j < 8; j++) {
            const int col = n0 + warp_n * 64 + j * 8 + 2 * tig;
            if constexpr (sizeof(CT) == 2) {
                *(__half2*)&C[(size_t)row * NCOLS + col] =
                    __floats2half2_rn(acc[i][j][0], acc[i][j][1]);
                *(__half2*)&C[(size_t)(row + 8) * NCOLS + col] =
                    __floats2half2_rn(acc[i][j][2], acc[i][j][3]);
            } else {
                *(float2*)&C[(size_t)row * NCOLS + col] =
                    make_float2(acc[i][j][0], acc[i][j][1]);
                *(float2*)&C[(size_t)(row + 8) * NCOLS + col] =
                    make_float2(acc[i][j][2], acc[i][j][3]);
            }
        }
    }
}

__global__ __launch_bounds__(256, 2) void qkv_gemm_kernel()
{
    hgemm_impl<QKV_COLS, DIM, __half>(g_xn_h, g_wqkv_h, g_qkv_h);
}

__global__ __launch_bounds__(256, 2) void out_gemm_kernel(float* __restrict__ out)
{
    hgemm_impl<DIM, DIM, float>(g_attn_h, g_wout_h, out);
}

// ---------------------------------------------------------------------------
// fp16 flash attention, cp.async double-buffered K/V tiles (64 keys).
// K staged [key][dim] (B-frags via non-trans LDSM), V staged [key][dim]
// (B-frags via trans LDSM). Softmax fp32.
// ---------------------------------------------------------------------------
__global__ __launch_bounds__(128) void flash_attn_kernel()
{
    __shared__ __half Ksm[2][64][72];   // row stride 144B = 9 quads
    __shared__ __half Vsm[2][64][72];

    const int tid  = threadIdx.x;
    const int lane = tid & 31;
    const int wid  = tid >> 5;
    const int g    = lane >> 2;
    const int tig  = lane & 3;

    const int bh = blockIdx.y;
    const int b  = bh >> 4, h = bh & 15;
    const int qrow0 = blockIdx.x * 128 + wid * 32;

    const __half* base = g_qkv_h + (size_t)b * N_SEQ * QKV_COLS;

    // Q fragments (scale by 0.125 in half2 — exact, power of two)
    uint32_t aq[2][4][4];
    {
        const __half2 qs = __floats2half2_rn(0.125f, 0.125f);
        #pragma unroll
        for (int mt = 0; mt < 2; mt++) {
            const __half* qlo = base + (size_t)(qrow0 + mt * 16 + g    ) * QKV_COLS + h * DHEAD;
            const __half* qhi = base + (size_t)(qrow0 + mt * 16 + g + 8) * QKV_COLS + h * DHEAD;
            #pragma unroll
            for (int kc = 0; kc < 4; kc++) {
                const int c = kc * 16 + 2 * tig;
                __half2 v0 = __hmul2(*(const __half2*)&qlo[c    ], qs);
                __half2 v1 = __hmul2(*(const __half2*)&qhi[c    ], qs);
                __half2 v2 = __hmul2(*(const __half2*)&qlo[c + 8], qs);
                __half2 v3 = __hmul2(*(const __half2*)&qhi[c + 8], qs);
                aq[mt][kc][0] = *(uint32_t*)&v0;
                aq[mt][kc][1] = *(uint32_t*)&v1;
                aq[mt][kc][2] = *(uint32_t*)&v2;
                aq[mt][kc][3] = *(uint32_t*)&v3;
            }
        }
    }

    const uint32_t sK = smem_u32(Ksm);
    const uint32_t sV = smem_u32(Vsm);

    // cp.async: 512 chunks per matrix (64 rows x 8), 4 each per thread
    auto issue = [&](int kb, int buf) {
        const uint32_t k_s = sK + buf * (64 * 72 * 2);
        const uint32_t v_s = sV + buf * (64 * 72 * 2);
        #pragma unroll
        for (int j = 0; j < 4; j++) {
            const int c = tid + j * 128;
            const int r = c >> 3, col = (c & 7) * 8;
            const __half* src = base + (size_t)(kb + r) * QKV_COLS + h * DHEAD + col;
            CP_ASYNC16(k_s + r * 144 + col * 2, src + 1024);
            CP_ASYNC16(v_s + r * 144 + col * 2, src + 2048);
        }
        CP_COMMIT();
    };

    // fragment bases (byte offsets added per stage)
    const uint32_t kb_off = ((lane & 7) + ((lane >> 4) & 1) * 8) * 144 + ((lane >> 3) & 1) * 16;
    const uint32_t vb_off = (lane & 15) * 144 + (lane >> 4) * 16;

    float Oa[2][8][4];
    #pragma unroll
    for (int mt = 0; mt < 2; mt++)
        #pragma unroll
        for (int dt = 0; dt < 8; dt++)
            #pragma unroll
            for (int r = 0; r < 4; r++) Oa[mt][dt][r] = 0.f;

    float m[2][2] = {{-INFINITY, -INFINITY}, {-INFINITY, -INFINITY}};
    float l[2][2] = {{0.f, 0.f}, {0.f, 0.f}};

    const int NT = N_SEQ / 64;
    issue(0, 0);
    int buf = 0;

    for (int i = 0; i < NT; i++) {
        if (i + 1 < NT) { issue((i + 1) * 64, buf ^ 1); CP_WAIT(1); }
        else            { CP_WAIT(0); }
        __syncthreads();

        const uint32_t kbase = sK + buf * (64 * 72 * 2) + kb_off;
        const uint32_t vbase = sV + buf * (64 * 72 * 2) + vb_off;

        // S = Q @ K^T
        float s[2][8][4];
        #pragma unroll
        for (int mt = 0; mt < 2; mt++)
            #pragma unroll
            for (int j = 0; j < 8; j++)
                #pragma unroll
                for (int r = 0; r < 4; r++) s[mt][j][r] = 0.f;

        #pragma unroll
        for (int kc = 0; kc < 4; kc++) {
            #pragma unroll
            for (int jp = 0; jp < 4; jp++) {
                uint32_t d0, d1, d2, d3;
                ldsm_x4(d0, d1, d2, d3, kbase + jp * 16 * 144 + kc * 32);
                mma_f16(s[0][2 * jp    ], aq[0][kc], d0, d1);
                mma_f16(s[1][2 * jp    ], aq[1][kc], d0, d1);
                mma_f16(s[0][2 * jp + 1], aq[0][kc], d2, d3);
                mma_f16(s[1][2 * jp + 1], aq[1][kc], d2, d3);
            }
        }

        // Online softmax
        float nm[2][2], alpha[2][2];
        #pragma unroll
        for (int mt = 0; mt < 2; mt++) {
            float mlo = m[mt][0], mhi = m[mt][1];
            #pragma unroll
            for (int j = 0; j < 8; j++) {
                mlo = fmaxf(mlo, fmaxf(s[mt][j][0], s[mt][j][1]));
                mhi = fmaxf(mhi, fmaxf(s[mt][j][2], s[mt][j][3]));
            }
            mlo = fmaxf(mlo, __shfl_xor_sync(0xFFFFFFFFu, mlo, 1));
            mlo = fmaxf(mlo, __shfl_xor_sync(0xFFFFFFFFu, mlo, 2));
            mhi = fmaxf(mhi, __shfl_xor_sync(0xFFFFFFFFu, mhi, 1));
            mhi = fmaxf(mhi, __shfl_xor_sync(0xFFFFFFFFu, mhi, 2));
            nm[mt][0] = mlo; nm[mt][1] = mhi;
            alpha[mt][0] = __expf(m[mt][0] - mlo);
            alpha[mt][1] = __expf(m[mt][1] - mhi);
            m[mt][0] = mlo; m[mt][1] = mhi;
        }

        uint32_t pa[2][4][4];
        #pragma unroll
        for (int mt = 0; mt < 2; mt++) {
            float rs_lo = 0.f, rs_hi = 0.f;
            #pragma unroll
            for (int jj = 0; jj < 4; jj++) {
                float p00 = __expf(s[mt][2*jj  ][0] - nm[mt][0]);
                float p01 = __expf(s[mt][2*jj  ][1] - nm[mt][0]);
                float p02 = __expf(s[mt][2*jj  ][2] - nm[mt][1]);
                float p03 = __expf(s[mt][2*jj  ][3] - nm[mt][1]);
                float p10 = __expf(s[mt][2*jj+1][0] - nm[mt][0]);
                float p11 = __expf(s[mt][2*jj+1][1] - nm[mt][0]);
                float p12 = __expf(s[mt][2*jj+1][2] - nm[mt][1]);
                float p13 = __expf(s[mt][2*jj+1][3] - nm[mt][1]);
                rs_lo += p00 + p01 + p10 + p11;
                rs_hi += p02 + p03 + p12 + p13;
                pa[mt][jj][0] = h2pack(p00, p01);
                pa[mt][jj][1] = h2pack(p02, p03);
                pa[mt][jj][2] = h2pack(p10, p11);
                pa[mt][jj][3] = h2pack(p12, p13);
            }
            l[mt][0] = l[mt][0] * alpha[mt][0] + rs_lo;
            l[mt][1] = l[mt][1] * alpha[mt][1] + rs_hi;
            #pragma unroll
            for (int dt = 0; dt < 8; dt++) {
                Oa[mt][dt][0] *= alpha[mt][0];
                Oa[mt][dt][1] *= alpha[mt][0];
                Oa[mt][dt][2] *= alpha[mt][1];
                Oa[mt][dt][3] *= alpha[mt][1];
            }
        }

        // O += P @ V   (V B-frags via trans LDSM on [key][dim])
        #pragma unroll
        for (int jj = 0; jj < 4; jj++) {
            #pragma unroll
            for (int dp = 0; dp < 4; dp++) {
                uint32_t d0, d1, d2, d3;
                ldsm_x4_trans(d0, d1, d2, d3, vbase + jj * 16 * 144 + dp * 32);
                mma_f16(Oa[0][2 * dp    ], pa[0][jj], d0, d1);
                mma_f16(Oa[1][2 * dp    ], pa[1][jj], d0, d1);
                mma_f16(Oa[0][2 * dp + 1], pa[0][jj], d2, d3);
                mma_f16(Oa[1][2 * dp + 1], pa[1][jj], d2, d3);
            }
        }
        __syncthreads();
        buf ^= 1;
    }

    #pragma unroll
    for (int mt = 0; mt < 2; mt++) {
        #pragma unroll
        for (int hh = 0; hh < 2; hh++) {
            float lv = l[mt][hh];
            lv += __shfl_xor_sync(0xFFFFFFFFu, lv, 1);
            lv += __shfl_xor_sync(0xFFFFFFFFu, lv, 2);
            l[mt][hh] = 1.0f / lv;
        }
    }

    #pragma unroll
    for (int mt = 0; mt < 2; mt++) {
        const int row_lo = qrow0 + mt * 16 + g;
        __half* olo = g_attn_h + (size_t)(b * N_SEQ + row_lo) * DIM + h * DHEAD;
        __half* ohi = olo + (size_t)8 * DIM;
        #pragma unroll
        for (int dt = 0; dt < 8; dt++) {
            const int col = dt * 8 + 2 * tig;
            *(__half2*)(olo + col) = __floats2half2_rn(Oa[mt][dt][0] * l[mt][0],
                                                       Oa[mt][dt][1] * l[mt][0]);
            *(__half2*)(ohi + col) = __floats2half2_rn(Oa[mt][dt][2] * l[mt][1],
                                                       Oa[mt][dt][3] * l[mt][1]);
        }
    }
}

// ---------------------------------------------------------------------------
extern "C" void kernel_launch(void* const* d_in, const int* in_sizes, int n_in,
                              void* d_out, int out_size)
{
    const float* x     = (const float*)d_in[0];
    const float* gamma = (const float*)d_in[1];
    const float* w_qkv = (const float*)d_in[2];
    const float* w_out = (const float*)d_in[3];
    float* out = (float*)d_out;

    __half* wqkv_h; cudaGetSymbolAddress((void**)&wqkv_h, g_wqkv_h);
    __half* wout_h; cudaGetSymbolAddress((void**)&wout_h, g_wout_h);

    f2h_kernel<<<DIM * QKV_COLS / 1024, 256>>>(w_qkv, wqkv_h);
    f2h_kernel<<<DIM * DIM / 1024, 256>>>(w_out, wout_h);
    rmsnorm_kernel<<<ROWS, 256>>>(x, gamma);
    qkv_gemm_kernel<<<dim3(QKV_COLS / 128, ROWS / 128), 256>>>();
    flash_attn_kernel<<<dim3(N_SEQ / 128, BATCH * HEADS), 128>>>();
    out_gemm_kernel<<<dim3(DIM / 128, ROWS / 128), 256>>>(out);
}

// round 7
// speedup vs baseline: 8.4370x; 1.0489x over previous
#include <cuda_runtime.h>
#include <cuda_fp16.h>
#include <math.h>
#include <stdint.h>

#define BATCH   2
#define N_SEQ   2048
#define DIM     1024
#define HEADS   16
#define DHEAD   64
#define ROWS    (BATCH * N_SEQ)   // 4096
#define QKV_COLS 3072

// fp16 scratch (no allocations allowed in kernel_launch)
__device__ __half g_xn_h[ROWS * DIM];           // 8 MB
__device__ __half g_qkv_h[ROWS * QKV_COLS];     // 24 MB
__device__ __half g_attn_h[ROWS * DIM];         // 8 MB
__device__ __half g_wqkv_h[DIM * QKV_COLS];     // 6 MB  [k][n]
__device__ __half g_wout_h[DIM * DIM];          // 2 MB  [k][n]

// ---------------------------------------------------------------------------
__device__ __forceinline__ uint32_t smem_u32(const void* p)
{
    return (uint32_t)__cvta_generic_to_shared(p);
}

#define CP_ASYNC16(dst, src) \
    asm volatile("cp.async.cg.shared.global [%0], [%1], 16;" :: "r"(dst), "l"(src))
#define CP_COMMIT() asm volatile("cp.async.commit_group;")
#define CP_WAIT(n)  asm volatile("cp.async.wait_group %0;" :: "n"(n))

__device__ __forceinline__ void ldsm_x4(
    uint32_t& r0, uint32_t& r1, uint32_t& r2, uint32_t& r3, uint32_t addr)
{
    asm volatile("ldmatrix.sync.aligned.m8n8.x4.shared.b16 {%0,%1,%2,%3}, [%4];"
                 : "=r"(r0), "=r"(r1), "=r"(r2), "=r"(r3) : "r"(addr));
}

__device__ __forceinline__ void ldsm_x4_trans(
    uint32_t& r0, uint32_t& r1, uint32_t& r2, uint32_t& r3, uint32_t addr)
{
    asm volatile("ldmatrix.sync.aligned.m8n8.x4.trans.shared.b16 {%0,%1,%2,%3}, [%4];"
                 : "=r"(r0), "=r"(r1), "=r"(r2), "=r"(r3) : "r"(addr));
}

__device__ __forceinline__ void mma_f16(
    float c[4], const uint32_t a[4], const uint32_t b0, const uint32_t b1)
{
    asm volatile(
        "mma.sync.aligned.m16n8k16.row.col.f32.f16.f16.f32 "
        "{%0,%1,%2,%3}, {%4,%5,%6,%7}, {%8,%9}, {%0,%1,%2,%3};"
        : "+f"(c[0]), "+f"(c[1]), "+f"(c[2]), "+f"(c[3])
        : "r"(a[0]), "r"(a[1]), "r"(a[2]), "r"(a[3]), "r"(b0), "r"(b1));
}

__device__ __forceinline__ uint32_t h2pack(float a, float b)
{
    __half2 h = __floats2half2_rn(a, b);
    return *(uint32_t*)&h;
}

// ---------------------------------------------------------------------------
// Fused prep: rmsnorm (blocks [0, ROWS)), w_qkv f2h (next 3072), w_out f2h
// (last 1024). One launch, all prep traffic concurrent.
// ---------------------------------------------------------------------------
#define WQKV_F2H_BLKS (DIM * QKV_COLS / 1024)   // 3072
#define WOUT_F2H_BLKS (DIM * DIM / 1024)        // 1024

__global__ __launch_bounds__(256) void prep_kernel(
    const float* __restrict__ x, const float* __restrict__ gamma,
    const float* __restrict__ w_qkv, const float* __restrict__ w_out)
{
    const int bid = blockIdx.x;
    const int tid = threadIdx.x;

    if (bid < ROWS) {
        // ---- RMSNorm row ----
        const int row = bid;
        const float4* xr = (const float4*)(x + (size_t)row * DIM);
        const float4* g4 = (const float4*)gamma;

        float4 v = xr[tid];
        float ss = v.x * v.x + v.y * v.y + v.z * v.z + v.w * v.w;
        #pragma unroll
        for (int o = 16; o > 0; o >>= 1) ss += __shfl_xor_sync(0xFFFFFFFFu, ss, o);

        __shared__ float warpsum[8];
        if ((tid & 31) == 0) warpsum[tid >> 5] = ss;
        __syncthreads();
        float sum = 0.f;
        #pragma unroll
        for (int i = 0; i < 8; i++) sum += warpsum[i];

        float norm = fmaxf(sqrtf(sum), 1e-12f);
        float inv  = 32.0f / norm;

        float4 g = g4[tid];
        __half2* xo = (__half2*)(g_xn_h + (size_t)row * DIM);
        xo[2 * tid    ] = __floats2half2_rn(v.x * inv * (g.x + 1.0f), v.y * inv * (g.y + 1.0f));
        xo[2 * tid + 1] = __floats2half2_rn(v.z * inv * (g.z + 1.0f), v.w * inv * (g.w + 1.0f));
    } else if (bid < ROWS + WQKV_F2H_BLKS) {
        const int i = (bid - ROWS) * 256 + tid;
        float4 v = ((const float4*)w_qkv)[i];
        __half2* o = (__half2*)g_wqkv_h;
        o[2 * i    ] = __floats2half2_rn(v.x, v.y);
        o[2 * i + 1] = __floats2half2_rn(v.z, v.w);
    } else {
        const int i = (bid - ROWS - WQKV_F2H_BLKS) * 256 + tid;
        float4 v = ((const float4*)w_out)[i];
        __half2* o = (__half2*)g_wout_h;
        o[2 * i    ] = __floats2half2_rn(v.x, v.y);
        o[2 * i + 1] = __floats2half2_rn(v.z, v.w);
    }
}

// ---------------------------------------------------------------------------
// fp16 GEMM: C[M,NCOLS] = A[M,KDIM] @ B[KDIM,NCOLS]; fp16 gmem operands.
// 128x128x32 tile, 256 threads, warp tile 32x64.
// 3-stage cp.async pipeline, ONE __syncthreads per k-iter.
// ---------------------------------------------------------------------------
#define GA_BUF (128 * 40 * 2)     // 10240 B per A stage
#define GB_BUF (32 * 136 * 2)     // 8704 B per B stage
#define GEMM_SMEM (3 * (GA_BUF + GB_BUF))   // 56832 B

template<int NCOLS, int KDIM, typename CT>
__device__ __forceinline__ void hgemm_impl(
    const __half* __restrict__ A, const __half* __restrict__ Bm, CT* __restrict__ C)
{
    extern __shared__ char smem[];
    const uint32_t sA = smem_u32(smem);            // 3 x GA_BUF
    const uint32_t sB = sA + 3 * GA_BUF;           // 3 x GB_BUF

    const int tid  = threadIdx.x;
    const int lane = tid & 31;
    const int wid  = tid >> 5;
    const int g    = lane >> 2;
    const int tig  = lane & 3;
    const int warp_m = wid & 3;
    const int warp_n = wid >> 2;

    const int m0 = blockIdx.y * 128;
    const int n0 = blockIdx.x * 128;

    const int ac0 = tid,  ac1 = tid + 256;
    const int aR0 = ac0 >> 2, aC0 = (ac0 & 3) * 8;
    const int aR1 = ac1 >> 2, aC1 = (ac1 & 3) * 8;
    const int bR0 = ac0 >> 4, bC0 = (ac0 & 15) * 8;
    const int bR1 = ac1 >> 4, bC1 = (ac1 & 15) * 8;

    auto issue = [&](int k0, int b) {
        const uint32_t a_s = sA + b * GA_BUF;
        const uint32_t b_s = sB + b * GB_BUF;
        CP_ASYNC16(a_s + aR0 * 80 + aC0 * 2,  A  + (size_t)(m0 + aR0) * KDIM + k0 + aC0);
        CP_ASYNC16(a_s + aR1 * 80 + aC1 * 2,  A  + (size_t)(m0 + aR1) * KDIM + k0 + aC1);
        CP_ASYNC16(b_s + bR0 * 272 + bC0 * 2, Bm + (size_t)(k0 + bR0) * NCOLS + n0 + bC0);
        CP_ASYNC16(b_s + bR1 * 272 + bC1 * 2, Bm + (size_t)(k0 + bR1) * NCOLS + n0 + bC1);
        CP_COMMIT();
    };

    float acc[2][8][4];
    #pragma unroll
    for (int i = 0; i < 2; i++)
        #pragma unroll
        for (int j = 0; j < 8; j++)
            #pragma unroll
            for (int r = 0; r < 4; r++) acc[i][j][r] = 0.f;

    const int NT = KDIM / 32;
    issue(0, 0);
    issue(32, 1);

    int buf = 0;
    for (int i = 0; i < NT; i++) {
        if (i + 1 < NT) { CP_WAIT(1); }
        else            { CP_WAIT(0); }
        __syncthreads();
        if (i + 2 < NT) {
            int nb = buf + 2; if (nb >= 3) nb -= 3;
            issue((i + 2) * 32, nb);
        }

        const uint32_t a_s = sA + buf * GA_BUF;
        const uint32_t b_s = sB + buf * GB_BUF;
        const uint32_t a_base = a_s + (warp_m * 32 + (lane & 15)) * 80 + (lane >> 4) * 16;
        const uint32_t b_base = b_s + (lane & 15) * 272 + (warp_n * 64 + (lane >> 4) * 8) * 2;

        #pragma unroll
        for (int kc = 0; kc < 2; kc++) {
            uint32_t a[2][4];
            ldsm_x4(a[0][0], a[0][1], a[0][2], a[0][3], a_base + kc * 32);
            ldsm_x4(a[1][0], a[1][1], a[1][2], a[1][3], a_base + 16 * 80 + kc * 32);

            uint32_t b[8][2];
            #pragma unroll
            for (int jp = 0; jp < 4; jp++) {
                uint32_t d0, d1, d2, d3;
                ldsm_x4_trans(d0, d1, d2, d3, b_base + kc * 16 * 272 + jp * 32);
                b[2 * jp    ][0] = d0; b[2 * jp    ][1] = d1;
                b[2 * jp + 1][0] = d2; b[2 * jp + 1][1] = d3;
            }

            #pragma unroll
            for (int j = 0; j < 8; j++) {
                mma_f16(acc[0][j], a[0], b[j][0], b[j][1]);
                mma_f16(acc[1][j], a[1], b[j][0], b[j][1]);
            }
        }
        if (++buf >= 3) buf = 0;
    }

    #pragma unroll
    for (int i = 0; i < 2; i++) {
        const int row = m0 + warp_m * 32 + i * 16 + g;
        #pragma unroll
        for (int j = 0; j < 8; j++) {
            const int col = n0 + warp_n * 64 + j * 8 + 2 * tig;
            if constexpr (sizeof(CT) == 2) {
                *(__half2*)&C[(size_t)row * NCOLS + col] =
                    __floats2half2_rn(acc[i][j][0], acc[i][j][1]);
                *(__half2*)&C[(size_t)(row + 8) * NCOLS + col] =
                    __floats2half2_rn(acc[i][j][2], acc[i][j][3]);
            } else {
                *(float2*)&C[(size_t)row * NCOLS + col] =
                    make_float2(acc[i][j][0], acc[i][j][1]);
                *(float2*)&C[(size_t)(row + 8) * NCOLS + col] =
                    make_float2(acc[i][j][2], acc[i][j][3]);
            }
        }
    }
}

__global__ __launch_bounds__(256, 2) void qkv_gemm_kernel()
{
    hgemm_impl<QKV_COLS, DIM, __half>(g_xn_h, g_wqkv_h, g_qkv_h);
}

__global__ __launch_bounds__(256, 2) void out_gemm_kernel(float* __restrict__ out)
{
    hgemm_impl<DIM, DIM, float>(g_attn_h, g_wout_h, out);
}

// ---------------------------------------------------------------------------
// fp16 flash attention, 3-stage cp.async, ONE sync per kv-tile (64 keys).
// ---------------------------------------------------------------------------
#define FK_BUF (64 * 72 * 2)   // 9216 B per K (or V) stage
#define ATTN_SMEM (6 * FK_BUF) // 55296 B

__global__ __launch_bounds__(128) void flash_attn_kernel()
{
    extern __shared__ char smem[];
    const uint32_t sK = smem_u32(smem);          // 3 x FK_BUF
    const uint32_t sV = sK + 3 * FK_BUF;         // 3 x FK_BUF

    const int tid  = threadIdx.x;
    const int lane = tid & 31;
    const int wid  = tid >> 5;
    const int g    = lane >> 2;
    const int tig  = lane & 3;

    const int bh = blockIdx.y;
    const int b  = bh >> 4, h = bh & 15;
    const int qrow0 = blockIdx.x * 128 + wid * 32;

    const __half* base = g_qkv_h + (size_t)b * N_SEQ * QKV_COLS;

    uint32_t aq[2][4][4];
    {
        const __half2 qs = __floats2half2_rn(0.125f, 0.125f);
        #pragma unroll
        for (int mt = 0; mt < 2; mt++) {
            const __half* qlo = base + (size_t)(qrow0 + mt * 16 + g    ) * QKV_COLS + h * DHEAD;
            const __half* qhi = base + (size_t)(qrow0 + mt * 16 + g + 8) * QKV_COLS + h * DHEAD;
            #pragma unroll
            for (int kc = 0; kc < 4; kc++) {
                const int c = kc * 16 + 2 * tig;
                __half2 v0 = __hmul2(*(const __half2*)&qlo[c    ], qs);
                __half2 v1 = __hmul2(*(const __half2*)&qhi[c    ], qs);
                __half2 v2 = __hmul2(*(const __half2*)&qlo[c + 8], qs);
                __half2 v3 = __hmul2(*(const __half2*)&qhi[c + 8], qs);
                aq[mt][kc][0] = *(uint32_t*)&v0;
                aq[mt][kc][1] = *(uint32_t*)&v1;
                aq[mt][kc][2] = *(uint32_t*)&v2;
                aq[mt][kc][3] = *(uint32_t*)&v3;
            }
        }
    }

    auto issue = [&](int kb, int bf) {
        const uint32_t k_s = sK + bf * FK_BUF;
        const uint32_t v_s = sV + bf * FK_BUF;
        #pragma unroll
        for (int j = 0; j < 4; j++) {
            const int c = tid + j * 128;
            const int r = c >> 3, col = (c & 7) * 8;
            const __half* src = base + (size_t)(kb + r) * QKV_COLS + h * DHEAD + col;
            CP_ASYNC16(k_s + r * 144 + col * 2, src + 1024);
            CP_ASYNC16(v_s + r * 144 + col * 2, src + 2048);
        }
        CP_COMMIT();
    };

    const uint32_t kb_off = ((lane & 7) + ((lane >> 4) & 1) * 8) * 144 + ((lane >> 3) & 1) * 16;
    const uint32_t vb_off = (lane & 15) * 144 + (lane >> 4) * 16;

    float Oa[2][8][4];
    #pragma unroll
    for (int mt = 0; mt < 2; mt++)
        #pragma unroll
        for (int dt = 0; dt < 8; dt++)
            #pragma unroll
            for (int r = 0; r < 4; r++) Oa[mt][dt][r] = 0.f;

    float m[2][2] = {{-INFINITY, -INFINITY}, {-INFINITY, -INFINITY}};
    float l[2][2] = {{0.f, 0.f}, {0.f, 0.f}};

    const int NT = N_SEQ / 64;
    issue(0, 0);
    issue(64, 1);

    int buf = 0;
    for (int i = 0; i < NT; i++) {
        if (i + 1 < NT) { CP_WAIT(1); }
        else            { CP_WAIT(0); }
        __syncthreads();
        if (i + 2 < NT) {
            int nb = buf + 2; if (nb >= 3) nb -= 3;
            issue((i + 2) * 64, nb);
        }

        const uint32_t kbase = sK + buf * FK_BUF + kb_off;
        const uint32_t vbase = sV + buf * FK_BUF + vb_off;

        float s[2][8][4];
        #pragma unroll
        for (int mt = 0; mt < 2; mt++)
            #pragma unroll
            for (int j = 0; j < 8; j++)
                #pragma unroll
                for (int r = 0; r < 4; r++) s[mt][j][r] = 0.f;

        #pragma unroll
        for (int kc = 0; kc < 4; kc++) {
            #pragma unroll
            for (int jp = 0; jp < 4; jp++) {
                uint32_t d0, d1, d2, d3;
                ldsm_x4(d0, d1, d2, d3, kbase + jp * 16 * 144 + kc * 32);
                mma_f16(s[0][2 * jp    ], aq[0][kc], d0, d1);
                mma_f16(s[1][2 * jp    ], aq[1][kc], d0, d1);
                mma_f16(s[0][2 * jp + 1], aq[0][kc], d2, d3);
                mma_f16(s[1][2 * jp + 1], aq[1][kc], d2, d3);
            }
        }

        float nm[2][2], alpha[2][2];
        #pragma unroll
        for (int mt = 0; mt < 2; mt++) {
            float mlo = m[mt][0], mhi = m[mt][1];
            #pragma unroll
            for (int j = 0; j < 8; j++) {
                mlo = fmaxf(mlo, fmaxf(s[mt][j][0], s[mt][j][1]));
                mhi = fmaxf(mhi, fmaxf(s[mt][j][2], s[mt][j][3]));
            }
            mlo = fmaxf(mlo, __shfl_xor_sync(0xFFFFFFFFu, mlo, 1));
            mlo = fmaxf(mlo, __shfl_xor_sync(0xFFFFFFFFu, mlo, 2));
            mhi = fmaxf(mhi, __shfl_xor_sync(0xFFFFFFFFu, mhi, 1));
            mhi = fmaxf(mhi, __shfl_xor_sync(0xFFFFFFFFu, mhi, 2));
            nm[mt][0] = mlo; nm[mt][1] = mhi;
            alpha[mt][0] = __expf(m[mt][0] - mlo);
            alpha[mt][1] = __expf(m[mt][1] - mhi);
            m[mt][0] = mlo; m[mt][1] = mhi;
        }

        uint32_t pa[2][4][4];
        #pragma unroll
        for (int mt = 0; mt < 2; mt++) {
            float rs_lo = 0.f, rs_hi = 0.f;
            #pragma unroll
            for (int jj = 0; jj < 4; jj++) {
                float p00 = __expf(s[mt][2*jj  ][0] - nm[mt][0]);
                float p01 = __expf(s[mt][2*jj  ][1] - nm[mt][0]);
                float p02 = __expf(s[mt][2*jj  ][2] - nm[mt][1]);
                float p03 = __expf(s[mt][2*jj  ][3] - nm[mt][1]);
                float p10 = __expf(s[mt][2*jj+1][0] - nm[mt][0]);
                float p11 = __expf(s[mt][2*jj+1][1] - nm[mt][0]);
                float p12 = __expf(s[mt][2*jj+1][2] - nm[mt][1]);
                float p13 = __expf(s[mt][2*jj+1][3] - nm[mt][1]);
                rs_lo += p00 + p01 + p10 + p11;
                rs_hi += p02 + p03 + p12 + p13;
                pa[mt][jj][0] = h2pack(p00, p01);
                pa[mt][jj][1] = h2pack(p02, p03);
                pa[mt][jj][2] = h2pack(p10, p11);
                pa[mt][jj][3] = h2pack(p12, p13);
            }
            l[mt][0] = l[mt][0] * alpha[mt][0] + rs_lo;
            l[mt][1] = l[mt][1] * alpha[mt][1] + rs_hi;
            #pragma unroll
            for (int dt = 0; dt < 8; dt++) {
                Oa[mt][dt][0] *= alpha[mt][0];
                Oa[mt][dt][1] *= alpha[mt][0];
                Oa[mt][dt][2] *= alpha[mt][1];
                Oa[mt][dt][3] *= alpha[mt][1];
            }
        }

        #pragma unroll
        for (int jj = 0; jj < 4; jj++) {
            #pragma unroll
            for (int dp = 0; dp < 4; dp++) {
                uint32_t d0, d1, d2, d3;
                ldsm_x4_trans(d0, d1, d2, d3, vbase + jj * 16 * 144 + dp * 32);
                mma_f16(Oa[0][2 * dp    ], pa[0][jj], d0, d1);
                mma_f16(Oa[1][2 * dp    ], pa[1][jj], d0, d1);
                mma_f16(Oa[0][2 * dp + 1], pa[0][jj], d2, d3);
                mma_f16(Oa[1][2 * dp + 1], pa[1][jj], d2, d3);
            }
        }
        if (++buf >= 3) buf = 0;
    }

    #pragma unroll
    for (int mt = 0; mt < 2; mt++) {
        #pragma unroll
        for (int hh = 0; hh < 2; hh++) {
            float lv = l[mt][hh];
            lv += __shfl_xor_sync(0xFFFFFFFFu, lv, 1);
            lv += __shfl_xor_sync(0xFFFFFFFFu, lv, 2);
            l[mt][hh] = 1.0f / lv;
        }
    }

    #pragma unroll
    for (int mt = 0; mt < 2; mt++) {
        const int row_lo = qrow0 + mt * 16 + g;
        __half* olo = g_attn_h + (size_t)(b * N_SEQ + row_lo) * DIM + h * DHEAD;
        __half* ohi = olo + (size_t)8 * DIM;
        #pragma unroll
        for (int dt = 0; dt < 8; dt++) {
            const int col = dt * 8 + 2 * tig;
            *(__half2*)(olo + col) = __floats2half2_rn(Oa[mt][dt][0] * l[mt][0],
                                                       Oa[mt][dt][1] * l[mt][0]);
            *(__half2*)(ohi + col) = __floats2half2_rn(Oa[mt][dt][2] * l[mt][1],
                                                       Oa[mt][dt][3] * l[mt][1]);
        }
    }
}

// ---------------------------------------------------------------------------
extern "C" void kernel_launch(void* const* d_in, const int* in_sizes, int n_in,
                              void* d_out, int out_size)
{
    const float* x     = (const float*)d_in[0];
    const float* gamma = (const float*)d_in[1];
    const float* w_qkv = (const float*)d_in[2];
    const float* w_out = (const float*)d_in[3];
    float* out = (float*)d_out;

    static bool attr_done = false;
    if (!attr_done) {
        cudaFuncSetAttribute(qkv_gemm_kernel,
                             cudaFuncAttributeMaxDynamicSharedMemorySize, GEMM_SMEM);
        cudaFuncSetAttribute(out_gemm_kernel,
                             cudaFuncAttributeMaxDynamicSharedMemorySize, GEMM_SMEM);
        cudaFuncSetAttribute(flash_attn_kernel,
                             cudaFuncAttributeMaxDynamicSharedMemorySize, ATTN_SMEM);
        attr_done = true;
    }

    prep_kernel<<<ROWS + WQKV_F2H_BLKS + WOUT_F2H_BLKS, 256>>>(x, gamma, w_qkv, w_out);
    qkv_gemm_kernel<<<dim3(QKV_COLS / 128, ROWS / 128), 256, GEMM_SMEM>>>();
    flash_attn_kernel<<<dim3(N_SEQ / 128, BATCH * HEADS), 128, ATTN_SMEM>>>();
    out_gemm_kernel<<<dim3(DIM / 128, ROWS / 128), 256, GEMM_SMEM>>>(out);
}